// round 9
// baseline (speedup 1.0000x reference)
#include <cuda_runtime.h>
#include <math.h>

#define T_SEQ 2048
#define C_DIM 1024
#define HEADS 16
#define KV_HEADS 4
#define HDIM 64
#define KV_DIM 512
#define WINDOW_SZ 512

typedef unsigned long long ull;

// ---- packed fp32x2 helpers (sm_100+ PTX; ptxas never auto-generates these) ----
__device__ __forceinline__ ull pdup(float x) {
    ull r;
    asm("mov.b64 %0, {%1, %1};" : "=l"(r) : "r"(__float_as_uint(x)));
    return r;
}
__device__ __forceinline__ void ffma2(ull& d, ull a, ull b) {
    asm("fma.rn.f32x2 %0, %1, %2, %0;" : "+l"(d) : "l"(a), "l"(b));
}
__device__ __forceinline__ void fmul2(ull& d, ull a) {
    asm("mul.rn.f32x2 %0, %0, %1;" : "+l"(d) : "l"(a));
}
__device__ __forceinline__ float2 unpk(ull v) {
    unsigned lo, hi;
    asm("mov.b64 {%0, %1}, %2;" : "=r"(lo), "=r"(hi) : "l"(v));
    return make_float2(__uint_as_float(lo), __uint_as_float(hi));
}

// Scratch (no cudaMalloc allowed)
__device__ float g_q[T_SEQ * C_DIM];    // 8 MB
__device__ float g_kv[T_SEQ * KV_DIM];  // 4 MB  (K: cols 0..255, V: cols 256..511)
__device__ float g_y[T_SEQ * C_DIM];    // 8 MB

// ---------------------------------------------------------------------------
// GEMM: C[M,N] = A[M,K] * B[N,K]^T  (both K-major). 128x128x8 tile, 256 thr,
// 8x8 microtile, double-buffered smem, packed-FFMA2 inner loop.
// ---------------------------------------------------------------------------
#define GBM 128
#define GBN 128
#define GBK 8
#define GST 132

__global__ __launch_bounds__(256, 2)
void gemm_tn(const float* __restrict__ A, const float* __restrict__ B,
             float* __restrict__ C, int M, int N, int K)
{
    __shared__ float As[2][GBK * GST];
    __shared__ float Bs[2][GBK * GST];
    const int tid = threadIdx.x;
    const int tx = tid & 15, ty = tid >> 4;
    const int m0 = blockIdx.y * GBM, n0 = blockIdx.x * GBN;
    const int lrow = tid >> 1, lcol = (tid & 1) * 4;

    const float* Ap = A + (size_t)(m0 + lrow) * K + lcol;
    const float* Bp = B + (size_t)(n0 + lrow) * K + lcol;

    float4 av = *reinterpret_cast<const float4*>(Ap);
    float4 bv = *reinterpret_cast<const float4*>(Bp);
    As[0][(lcol + 0) * GST + lrow] = av.x;
    As[0][(lcol + 1) * GST + lrow] = av.y;
    As[0][(lcol + 2) * GST + lrow] = av.z;
    As[0][(lcol + 3) * GST + lrow] = av.w;
    Bs[0][(lcol + 0) * GST + lrow] = bv.x;
    Bs[0][(lcol + 1) * GST + lrow] = bv.y;
    Bs[0][(lcol + 2) * GST + lrow] = bv.z;
    Bs[0][(lcol + 3) * GST + lrow] = bv.w;
    __syncthreads();

    ull acc2[8][4];  // [row][col-pair]: cols (4tx+2j, 4tx+2j+1), j>=2 -> +64
#pragma unroll
    for (int i = 0; i < 8; i++)
#pragma unroll
        for (int j = 0; j < 4; j++) acc2[i][j] = 0ull;  // bits(0,0) == (0.f,0.f)

    int buf = 0;
    for (int k0 = 0; k0 < K; k0 += GBK) {
        const bool hn = (k0 + GBK) < K;
        if (hn) {
            av = *reinterpret_cast<const float4*>(Ap + k0 + GBK);
            bv = *reinterpret_cast<const float4*>(Bp + k0 + GBK);
        }
#pragma unroll
        for (int kk = 0; kk < GBK; kk++) {
            float4 t0 = *reinterpret_cast<const float4*>(&As[buf][kk * GST + 4 * ty]);
            float4 t1 = *reinterpret_cast<const float4*>(&As[buf][kk * GST + 4 * ty + 64]);
            ulonglong2 u0 = *reinterpret_cast<const ulonglong2*>(&Bs[buf][kk * GST + 4 * tx]);
            ulonglong2 u1 = *reinterpret_cast<const ulonglong2*>(&Bs[buf][kk * GST + 4 * tx + 64]);
            ull aa[8] = {pdup(t0.x), pdup(t0.y), pdup(t0.z), pdup(t0.w),
                         pdup(t1.x), pdup(t1.y), pdup(t1.z), pdup(t1.w)};
            ull bb[4] = {u0.x, u0.y, u1.x, u1.y};
#pragma unroll
            for (int i = 0; i < 8; i++)
#pragma unroll
                for (int j = 0; j < 4; j++) ffma2(acc2[i][j], aa[i], bb[j]);
        }
        if (hn) {
            const int nb = buf ^ 1;
            As[nb][(lcol + 0) * GST + lrow] = av.x;
            As[nb][(lcol + 1) * GST + lrow] = av.y;
            As[nb][(lcol + 2) * GST + lrow] = av.z;
            As[nb][(lcol + 3) * GST + lrow] = av.w;
            Bs[nb][(lcol + 0) * GST + lrow] = bv.x;
            Bs[nb][(lcol + 1) * GST + lrow] = bv.y;
            Bs[nb][(lcol + 2) * GST + lrow] = bv.z;
            Bs[nb][(lcol + 3) * GST + lrow] = bv.w;
            __syncthreads();
            buf = nb;
        }
    }

#pragma unroll
    for (int i = 0; i < 8; i++) {
        int r = m0 + 4 * ty + (i & 3) + ((i >= 4) ? 64 : 0);
        float2 c0 = unpk(acc2[i][0]), c1 = unpk(acc2[i][1]);
        float2 c2 = unpk(acc2[i][2]), c3 = unpk(acc2[i][3]);
        *reinterpret_cast<float4*>(&C[(size_t)r * N + n0 + 4 * tx]) =
            make_float4(c0.x, c0.y, c1.x, c1.y);
        *reinterpret_cast<float4*>(&C[(size_t)r * N + n0 + 64 + 4 * tx]) =
            make_float4(c2.x, c2.y, c3.x, c3.y);
    }
}

// ---------------------------------------------------------------------------
// QK L2-normalize + RoPE. One warp per (t, head).
// ---------------------------------------------------------------------------
__global__ void norm_rope_kernel(float* __restrict__ q, float* __restrict__ kvbuf)
{
    const int t = blockIdx.x;
    const int h = blockIdx.y;
    const int lane = threadIdx.x;
    float* base = (h < HEADS)
        ? q + (size_t)t * C_DIM + h * HDIM
        : kvbuf + (size_t)t * KV_DIM + (h - HEADS) * HDIM;

    float a = base[lane];
    float b = base[lane + 32];
    float ss = a * a + b * b;
#pragma unroll
    for (int off = 16; off > 0; off >>= 1)
        ss += __shfl_xor_sync(0xffffffffu, ss, off);
    float inv = 1.f / (sqrtf(ss) + 1e-6f);

    float theta = powf(10000.f, -(float)lane * (1.f / 32.f));
    float ang = (float)t * theta;
    float sv, cv;
    sincosf(ang, &sv, &cv);

    base[lane]      = (a * cv - b * sv) * inv;
    base[lane + 32] = (b * cv + a * sv) * inv;
}

// ---------------------------------------------------------------------------
// Windowed flash attention v3: same tiling as v2 (64x64 tiles, 128 thr,
// 4x8 microtile) but QK / PV inner loops and O-rescale use packed FFMA2.
// ---------------------------------------------------------------------------
__global__ __launch_bounds__(128, 4)
void attn_kernel(const float* __restrict__ q, const float* __restrict__ kv,
                 float* __restrict__ y)
{
    __shared__ float Qt[64 * 64];  // [kk][r]
    __shared__ float KP[64 * 64];  // Kt: [kk][c]; later P: [k][r] chunk-swizzled
    __shared__ float Vs[64 * 64];  // [k][c]

    const int mt = blockIdx.x;
    const int h = blockIdx.y;
    const int kvh = h >> 2;
    const int m0 = mt * 64;
    const int tid = threadIdx.x;
    const int tx = tid & 7, ty = tid >> 3;

#pragma unroll
    for (int it = 0; it < 8; it++) {
        int idx = tid + it * 128;
        int r = idx & 63, kc = idx >> 6;
        float4 v = *reinterpret_cast<const float4*>(
            &q[(size_t)(m0 + r) * C_DIM + h * HDIM + kc * 4]);
        Qt[(kc * 4 + 0) * 64 + r] = v.x;
        Qt[(kc * 4 + 1) * 64 + r] = v.y;
        Qt[(kc * 4 + 2) * 64 + r] = v.z;
        Qt[(kc * 4 + 3) * 64 + r] = v.w;
    }

    ull o2[4][4];  // [row][col-pair]
    float m_i[4], l_i[4];
#pragma unroll
    for (int i = 0; i < 4; i++) {
        m_i[i] = -1e30f; l_i[i] = 0.f;
#pragma unroll
        for (int j = 0; j < 4; j++) o2[i][j] = 0ull;
    }

    const int nstart = (mt >= 8) ? (mt - 8) : 0;
    for (int nt = nstart; nt <= mt; nt++) {
        const int n0 = nt * 64;
        __syncthreads();  // prior-iter P/V reads done before overwrite

#pragma unroll
        for (int it = 0; it < 8; it++) {
            int idx = tid + it * 128;
            int c = idx & 63, kc = idx >> 6;
            float4 v = *reinterpret_cast<const float4*>(
                &kv[(size_t)(n0 + c) * KV_DIM + kvh * HDIM + kc * 4]);
            KP[(kc * 4 + 0) * 64 + c] = v.x;
            KP[(kc * 4 + 1) * 64 + c] = v.y;
            KP[(kc * 4 + 2) * 64 + c] = v.z;
            KP[(kc * 4 + 3) * 64 + c] = v.w;
        }
#pragma unroll
        for (int it = 0; it < 8; it++) {
            int idx = tid + it * 128;
            int k = idx >> 4, c4 = (idx & 15) * 4;
            *reinterpret_cast<float4*>(&Vs[k * 64 + c4]) =
                *reinterpret_cast<const float4*>(
                    &kv[(size_t)(n0 + k) * KV_DIM + 256 + kvh * HDIM + c4]);
        }
        __syncthreads();

        // S = Q K^T (packed): per kk, 3x LDS.128 + 4 packs + 16 FFMA2 = 32 FMA
        ull s2[4][4];
#pragma unroll
        for (int i = 0; i < 4; i++)
#pragma unroll
            for (int j = 0; j < 4; j++) s2[i][j] = 0ull;

        const float* qp = Qt + 4 * ty;
        const float* kp = KP + 8 * tx;
#pragma unroll 8
        for (int kk = 0; kk < 64; kk++) {
            float4 a4 = *reinterpret_cast<const float4*>(qp + kk * 64);
            ulonglong2 b0 = *reinterpret_cast<const ulonglong2*>(kp + kk * 64);
            ulonglong2 b1 = *reinterpret_cast<const ulonglong2*>(kp + kk * 64 + 4);
            ull aa[4] = {pdup(a4.x), pdup(a4.y), pdup(a4.z), pdup(a4.w)};
            ull bb[4] = {b0.x, b0.y, b1.x, b1.y};
#pragma unroll
            for (int i = 0; i < 4; i++)
#pragma unroll
                for (int j = 0; j < 4; j++) ffma2(s2[i][j], aa[i], bb[j]);
        }

        // unpack, scale + mask (boundary tiles only)
        float s[4][8];
        const bool needmask = (nt == mt) || (nt == mt - 8);
#pragma unroll
        for (int i = 0; i < 4; i++)
#pragma unroll
            for (int jp = 0; jp < 4; jp++) {
                float2 f = unpk(s2[i][jp]);
                s[i][2 * jp] = f.x;
                s[i][2 * jp + 1] = f.y;
            }
#pragma unroll
        for (int i = 0; i < 4; i++)
#pragma unroll
            for (int j = 0; j < 8; j++) {
                float v = s[i][j] * 0.125f;  // 1/sqrt(64)
                if (needmask) {
                    int qr = m0 + 4 * ty + i;
                    int kc = n0 + 8 * tx + j;
                    if (kc > qr || kc <= qr - WINDOW_SZ) v = -1e30f;
                }
                s[i][j] = v;
            }

        // online softmax; row owned by 8 consecutive lanes (same ty)
#pragma unroll
        for (int i = 0; i < 4; i++) {
            float tmax = s[i][0];
#pragma unroll
            for (int j = 1; j < 8; j++) tmax = fmaxf(tmax, s[i][j]);
#pragma unroll
            for (int off = 4; off > 0; off >>= 1)
                tmax = fmaxf(tmax, __shfl_xor_sync(0xffffffffu, tmax, off));
            float mn = fmaxf(m_i[i], tmax);
            float corr = __expf(m_i[i] - mn);
            m_i[i] = mn;
            float rsum = 0.f;
#pragma unroll
            for (int j = 0; j < 8; j++) {
                float p = __expf(s[i][j] - mn);
                s[i][j] = p;
                rsum += p;
            }
#pragma unroll
            for (int off = 4; off > 0; off >>= 1)
                rsum += __shfl_xor_sync(0xffffffffu, rsum, off);
            l_i[i] = l_i[i] * corr + rsum;
            ull cd = pdup(corr);
#pragma unroll
            for (int j = 0; j < 4; j++) fmul2(o2[i][j], cd);
        }

        __syncthreads();  // all QK reads of KP done -> overlay P
#pragma unroll
        for (int j = 0; j < 8; j++) {
            int k = 8 * tx + j;
            int ch = ty ^ ((k >> 2) & 15);
            *reinterpret_cast<float4*>(&KP[k * 64 + 4 * ch]) =
                make_float4(s[0][j], s[1][j], s[2][j], s[3][j]);
        }
        __syncthreads();

        // O += P @ V (packed)
#pragma unroll 8
        for (int k = 0; k < 64; k++) {
            float4 p4 = *reinterpret_cast<const float4*>(
                &KP[k * 64 + 4 * (ty ^ ((k >> 2) & 15))]);
            ulonglong2 v0 = *reinterpret_cast<const ulonglong2*>(&Vs[k * 64 + 8 * tx]);
            ulonglong2 v1 = *reinterpret_cast<const ulonglong2*>(&Vs[k * 64 + 8 * tx + 4]);
            ull pp[4] = {pdup(p4.x), pdup(p4.y), pdup(p4.z), pdup(p4.w)};
            ull vv[4] = {v0.x, v0.y, v1.x, v1.y};
#pragma unroll
            for (int i = 0; i < 4; i++)
#pragma unroll
                for (int j = 0; j < 4; j++) ffma2(o2[i][j], pp[i], vv[j]);
        }
    }

#pragma unroll
    for (int i = 0; i < 4; i++) {
        float inv = 1.f / l_i[i];
        int qr = m0 + 4 * ty + i;
        float2 f0 = unpk(o2[i][0]), f1 = unpk(o2[i][1]);
        float2 f2 = unpk(o2[i][2]), f3 = unpk(o2[i][3]);
        *reinterpret_cast<float4*>(&y[(size_t)qr * C_DIM + h * HDIM + 8 * tx]) =
            make_float4(f0.x * inv, f0.y * inv, f1.x * inv, f1.y * inv);
        *reinterpret_cast<float4*>(&y[(size_t)qr * C_DIM + h * HDIM + 8 * tx + 4]) =
            make_float4(f2.x * inv, f2.y * inv, f3.x * inv, f3.y * inv);
    }
}

// ---------------------------------------------------------------------------
extern "C" void kernel_launch(void* const* d_in, const int* in_sizes, int n_in,
                              void* d_out, int out_size)
{
    const float* x     = (const float*)d_in[0];
    const float* Wq    = (const float*)d_in[1];
    const float* Wkv   = (const float*)d_in[2];
    const float* Wproj = (const float*)d_in[3];
    float* out = (float*)d_out;

    float *gq, *gkv, *gy;
    cudaGetSymbolAddress((void**)&gq, g_q);
    cudaGetSymbolAddress((void**)&gkv, g_kv);
    cudaGetSymbolAddress((void**)&gy, g_y);

    gemm_tn<<<dim3(C_DIM / GBN, T_SEQ / GBM), 256>>>(x, Wq, gq, T_SEQ, C_DIM, C_DIM);
    gemm_tn<<<dim3(KV_DIM / GBN, T_SEQ / GBM), 256>>>(x, Wkv, gkv, T_SEQ, KV_DIM, C_DIM);
    norm_rope_kernel<<<dim3(T_SEQ, HEADS + KV_HEADS), 32>>>(gq, gkv);
    attn_kernel<<<dim3(T_SEQ / 64, HEADS), 128>>>(gq, gkv, gy);
    gemm_tn<<<dim3(C_DIM / GBN, T_SEQ / GBM), 256>>>(gy, Wproj, out, T_SEQ, C_DIM, C_DIM);
}

// round 11
// speedup vs baseline: 2.2615x; 2.2615x over previous
#include <cuda_runtime.h>
#include <cuda_bf16.h>
#include <math.h>

#define T_SEQ 2048
#define C_DIM 1024
#define HEADS 16
#define KV_HEADS 4
#define HDIM 64
#define KV_DIM 512
#define WINDOW_SZ 512

typedef unsigned long long ull;

// ---------------- scratch (no cudaMalloc allowed) ----------------
__device__ float g_q[T_SEQ * C_DIM];
__device__ float g_kv[T_SEQ * KV_DIM];
__device__ float g_y[T_SEQ * C_DIM];

__device__ __nv_bfloat16 g_xh[T_SEQ * C_DIM], g_xl[T_SEQ * C_DIM];
__device__ __nv_bfloat16 g_wqh[C_DIM * C_DIM], g_wql[C_DIM * C_DIM];
__device__ __nv_bfloat16 g_wkh[KV_DIM * C_DIM], g_wkl[KV_DIM * C_DIM];
__device__ __nv_bfloat16 g_wph[C_DIM * C_DIM], g_wpl[C_DIM * C_DIM];
__device__ __nv_bfloat16 g_yh[T_SEQ * C_DIM], g_yl[T_SEQ * C_DIM];

// ---------------- PTX helpers (all baseline-arch: sm_80/75 era) ----------------
__device__ __forceinline__ unsigned smem_u32(const void* p) {
    unsigned a;
    asm("{ .reg .u64 t; cvta.to.shared.u64 t, %1; cvt.u32.u64 %0, t; }"
        : "=r"(a) : "l"(p));
    return a;
}
__device__ __forceinline__ void cp_async16(unsigned dst, const void* src) {
    asm volatile("cp.async.cg.shared.global [%0], [%1], 16;\n"
                 :: "r"(dst), "l"(src) : "memory");
}
__device__ __forceinline__ void ldm4(unsigned addr, unsigned& r0, unsigned& r1,
                                     unsigned& r2, unsigned& r3) {
    asm volatile("ldmatrix.sync.aligned.m8n8.x4.shared.b16 {%0,%1,%2,%3}, [%4];"
                 : "=r"(r0), "=r"(r1), "=r"(r2), "=r"(r3) : "r"(addr));
}
__device__ __forceinline__ void mma16816(float* c, const unsigned* a,
                                         unsigned b0, unsigned b1) {
    asm volatile("mma.sync.aligned.m16n8k16.row.col.f32.bf16.bf16.f32 "
                 "{%0,%1,%2,%3}, {%4,%5,%6,%7}, {%8,%9}, {%0,%1,%2,%3};"
                 : "+f"(c[0]), "+f"(c[1]), "+f"(c[2]), "+f"(c[3])
                 : "r"(a[0]), "r"(a[1]), "r"(a[2]), "r"(a[3]), "r"(b0), "r"(b1));
}

// ---------------------------------------------------------------------------
// split-bf16 conversion: hi = bf16(v), lo = bf16(v - hi). Vectorized by 4.
// ---------------------------------------------------------------------------
__global__ void cvt_split(const float* __restrict__ in,
                          __nv_bfloat16* __restrict__ hi,
                          __nv_bfloat16* __restrict__ lo, int n4)
{
    int i = blockIdx.x * blockDim.x + threadIdx.x;
    if (i >= n4) return;
    float4 v = reinterpret_cast<const float4*>(in)[i];
    __nv_bfloat16 h0 = __float2bfloat16(v.x), h1 = __float2bfloat16(v.y);
    __nv_bfloat16 h2 = __float2bfloat16(v.z), h3 = __float2bfloat16(v.w);
    __nv_bfloat16 l0 = __float2bfloat16(v.x - __bfloat162float(h0));
    __nv_bfloat16 l1 = __float2bfloat16(v.y - __bfloat162float(h1));
    __nv_bfloat16 l2 = __float2bfloat16(v.z - __bfloat162float(h2));
    __nv_bfloat16 l3 = __float2bfloat16(v.w - __bfloat162float(h3));
    reinterpret_cast<__nv_bfloat162*>(hi)[2 * i]     = __nv_bfloat162(h0, h1);
    reinterpret_cast<__nv_bfloat162*>(hi)[2 * i + 1] = __nv_bfloat162(h2, h3);
    reinterpret_cast<__nv_bfloat162*>(lo)[2 * i]     = __nv_bfloat162(l0, l1);
    reinterpret_cast<__nv_bfloat162*>(lo)[2 * i + 1] = __nv_bfloat162(l2, l3);
}

// ---------------------------------------------------------------------------
// HMMA split-bf16 GEMM: C[M,N] = A*B^T, A[M,1024], B[N,1024] as bf16 hi/lo.
// 128x128 CTA tile, 8 warps (2x4), warp tile 64x32, K-chunk 32, double-buffer.
// smem tile rows: 32 bf16 = 64B = 4x16B chunks, swizzle chunk'=(c+(r>>1))&3
// (conflict-free for cp.async stores and ldmatrix reads).
// Accumulate hh + hl + lh in fp32 (lo*lo dropped, ~6e-5 relative).
// ---------------------------------------------------------------------------
#define CHUNK_BYTES 32768   // 4 tiles (Ah,Al,Bh,Bl) x 8KB

__global__ __launch_bounds__(256)
void gemm_tc(const __nv_bfloat16* __restrict__ Ah, const __nv_bfloat16* __restrict__ Al,
             const __nv_bfloat16* __restrict__ Bh, const __nv_bfloat16* __restrict__ Bl,
             float* __restrict__ C, int Nld)
{
    extern __shared__ __align__(16) unsigned char dsmem[];
    const unsigned sbase = smem_u32(dsmem);

    const int tid = threadIdx.x;
    const int lane = tid & 31, wid = tid >> 5;
    const int m0 = blockIdx.y * 128, n0 = blockIdx.x * 128;
    const int warp_m = (wid & 1) * 64, warp_n = (wid >> 1) * 32;

    // ldmatrix lane->element maps
    const int arow = lane & 15, aoff = lane >> 4;              // A: rows 0-15, +k-chunk
    const int brow = (lane & 7) + ((lane >> 4) << 3);          // B: n rows 0-7 / 8-15
    const int boff = (lane >> 3) & 1;                          //    +k-chunk

    float acc[4][4][4];
#pragma unroll
    for (int mf = 0; mf < 4; mf++)
#pragma unroll
        for (int nf = 0; nf < 4; nf++)
#pragma unroll
            for (int r = 0; r < 4; r++) acc[mf][nf][r] = 0.f;

    // ---- fill one K-chunk into a buffer (2048 x 16B cp.async) ----
    auto fill = [&](int kc, unsigned bufbase) {
#pragma unroll
        for (int i = 0; i < 8; i++) {
            int idx = tid + i * 256;
            int tile = idx >> 9;              // 0:Ah 1:Al 2:Bh 3:Bl
            int e = idx & 511;
            int r = e >> 2, c = e & 3;
            const __nv_bfloat16* srcb =
                (tile == 0) ? Ah : (tile == 1) ? Al : (tile == 2) ? Bh : Bl;
            int row = ((tile < 2) ? m0 : n0) + r;
            const __nv_bfloat16* src = srcb + (size_t)row * 1024 + kc * 32 + c * 8;
            unsigned dst = bufbase + tile * 8192 + r * 64 + (((c + (r >> 1)) & 3) << 4);
            cp_async16(dst, src);
        }
        asm volatile("cp.async.commit_group;\n" ::: "memory");
    };

    fill(0, sbase);

    for (int kc = 0; kc < 32; kc++) {
        const unsigned cur = sbase + (kc & 1) * CHUNK_BYTES;
        if (kc + 1 < 32) {
            fill(kc + 1, sbase + ((kc + 1) & 1) * CHUNK_BYTES);
            asm volatile("cp.async.wait_group 1;\n" ::: "memory");
        } else {
            asm volatile("cp.async.wait_group 0;\n" ::: "memory");
        }
        __syncthreads();

        const unsigned aH = cur, aL = cur + 8192, bH = cur + 16384, bL = cur + 24576;
#pragma unroll
        for (int ks = 0; ks < 2; ks++) {
            unsigned ah[4][4], al[4][4], bh[2][4], bl[2][4];
#pragma unroll
            for (int mf = 0; mf < 4; mf++) {
                int row = warp_m + mf * 16 + arow;
                int c = ks * 2 + aoff;
                unsigned off = row * 64 + (((c + (row >> 1)) & 3) << 4);
                ldm4(aH + off, ah[mf][0], ah[mf][1], ah[mf][2], ah[mf][3]);
                ldm4(aL + off, al[mf][0], al[mf][1], al[mf][2], al[mf][3]);
            }
#pragma unroll
            for (int p = 0; p < 2; p++) {
                int row = warp_n + p * 16 + brow;
                int c = ks * 2 + boff;
                unsigned off = row * 64 + (((c + (row >> 1)) & 3) << 4);
                ldm4(bH + off, bh[p][0], bh[p][1], bh[p][2], bh[p][3]);
                ldm4(bL + off, bl[p][0], bl[p][1], bl[p][2], bl[p][3]);
            }
#pragma unroll
            for (int mf = 0; mf < 4; mf++)
#pragma unroll
                for (int p = 0; p < 2; p++) {
                    // n-frag 2p: regs {0,1}; n-frag 2p+1: regs {2,3}
                    mma16816(acc[mf][2 * p],     ah[mf], bh[p][0], bh[p][1]); // hh
                    mma16816(acc[mf][2 * p],     ah[mf], bl[p][0], bl[p][1]); // hl
                    mma16816(acc[mf][2 * p],     al[mf], bh[p][0], bh[p][1]); // lh
                    mma16816(acc[mf][2 * p + 1], ah[mf], bh[p][2], bh[p][3]);
                    mma16816(acc[mf][2 * p + 1], ah[mf], bl[p][2], bl[p][3]);
                    mma16816(acc[mf][2 * p + 1], al[mf], bh[p][2], bh[p][3]);
                }
        }
        __syncthreads();
    }

    // epilogue: c-frag rows lane>>2 (+8), cols 2*(lane&3)
#pragma unroll
    for (int mf = 0; mf < 4; mf++)
#pragma unroll
        for (int nf = 0; nf < 4; nf++) {
            int row = m0 + warp_m + mf * 16 + (lane >> 2);
            int col = n0 + warp_n + nf * 8 + (lane & 3) * 2;
            *reinterpret_cast<float2*>(&C[(size_t)row * Nld + col]) =
                make_float2(acc[mf][nf][0], acc[mf][nf][1]);
            *reinterpret_cast<float2*>(&C[(size_t)(row + 8) * Nld + col]) =
                make_float2(acc[mf][nf][2], acc[mf][nf][3]);
        }
}

// ---------------------------------------------------------------------------
// QK L2-normalize + RoPE. One warp per (t, head).
// ---------------------------------------------------------------------------
__global__ void norm_rope_kernel(float* __restrict__ q, float* __restrict__ kvbuf)
{
    const int t = blockIdx.x;
    const int h = blockIdx.y;
    const int lane = threadIdx.x;
    float* base = (h < HEADS)
        ? q + (size_t)t * C_DIM + h * HDIM
        : kvbuf + (size_t)t * KV_DIM + (h - HEADS) * HDIM;

    float a = base[lane];
    float b = base[lane + 32];
    float ss = a * a + b * b;
#pragma unroll
    for (int off = 16; off > 0; off >>= 1)
        ss += __shfl_xor_sync(0xffffffffu, ss, off);
    float inv = 1.f / (sqrtf(ss) + 1e-6f);

    float theta = powf(10000.f, -(float)lane * (1.f / 32.f));
    float ang = (float)t * theta;
    float sv, cv;
    sincosf(ang, &sv, &cv);

    base[lane]      = (a * cv - b * sv) * inv;
    base[lane + 32] = (b * cv + a * sv) * inv;
}

// ---------------------------------------------------------------------------
// Windowed flash attention (round-8 best). 128 thr, 64x64 tiles, 4x8 microtile.
// ---------------------------------------------------------------------------
__global__ __launch_bounds__(128, 4)
void attn_kernel(const float* __restrict__ q, const float* __restrict__ kv,
                 float* __restrict__ y)
{
    __shared__ float Qt[64 * 64];
    __shared__ float KP[64 * 64];
    __shared__ float Vs[64 * 64];

    const int mt = blockIdx.x;
    const int h = blockIdx.y;
    const int kvh = h >> 2;
    const int m0 = mt * 64;
    const int tid = threadIdx.x;
    const int tx = tid & 7, ty = tid >> 3;

#pragma unroll
    for (int it = 0; it < 8; it++) {
        int idx = tid + it * 128;
        int r = idx & 63, kc = idx >> 6;
        float4 v = *reinterpret_cast<const float4*>(
            &q[(size_t)(m0 + r) * C_DIM + h * HDIM + kc * 4]);
        Qt[(kc * 4 + 0) * 64 + r] = v.x;
        Qt[(kc * 4 + 1) * 64 + r] = v.y;
        Qt[(kc * 4 + 2) * 64 + r] = v.z;
        Qt[(kc * 4 + 3) * 64 + r] = v.w;
    }

    float o[4][8];
    float m_i[4], l_i[4];
#pragma unroll
    for (int i = 0; i < 4; i++) {
        m_i[i] = -1e30f; l_i[i] = 0.f;
#pragma unroll
        for (int j = 0; j < 8; j++) o[i][j] = 0.f;
    }

    const int nstart = (mt >= 8) ? (mt - 8) : 0;
    for (int nt = nstart; nt <= mt; nt++) {
        const int n0 = nt * 64;
        __syncthreads();

#pragma unroll
        for (int it = 0; it < 8; it++) {
            int idx = tid + it * 128;
            int c = idx & 63, kc = idx >> 6;
            float4 v = *reinterpret_cast<const float4*>(
                &kv[(size_t)(n0 + c) * KV_DIM + kvh * HDIM + kc * 4]);
            KP[(kc * 4 + 0) * 64 + c] = v.x;
            KP[(kc * 4 + 1) * 64 + c] = v.y;
            KP[(kc * 4 + 2) * 64 + c] = v.z;
            KP[(kc * 4 + 3) * 64 + c] = v.w;
        }
#pragma unroll
        for (int it = 0; it < 8; it++) {
            int idx = tid + it * 128;
            int k = idx >> 4, c4 = (idx & 15) * 4;
            *reinterpret_cast<float4*>(&Vs[k * 64 + c4]) =
                *reinterpret_cast<const float4*>(
                    &kv[(size_t)(n0 + k) * KV_DIM + 256 + kvh * HDIM + c4]);
        }
        __syncthreads();

        float s[4][8];
#pragma unroll
        for (int i = 0; i < 4; i++)
#pragma unroll
            for (int j = 0; j < 8; j++) s[i][j] = 0.f;

        const float* qp = Qt + 4 * ty;
        const float* kp = KP + 8 * tx;
#pragma unroll 8
        for (int kk = 0; kk < 64; kk++) {
            float4 a4 = *reinterpret_cast<const float4*>(qp + kk * 64);
            float4 b0 = *reinterpret_cast<const float4*>(kp + kk * 64);
            float4 b1 = *reinterpret_cast<const float4*>(kp + kk * 64 + 4);
            float a[4] = {a4.x, a4.y, a4.z, a4.w};
            float b[8] = {b0.x, b0.y, b0.z, b0.w, b1.x, b1.y, b1.z, b1.w};
#pragma unroll
            for (int i = 0; i < 4; i++)
#pragma unroll
                for (int j = 0; j < 8; j++) s[i][j] += a[i] * b[j];
        }

        const bool needmask = (nt == mt) || (nt == mt - 8);
#pragma unroll
        for (int i = 0; i < 4; i++)
#pragma unroll
            for (int j = 0; j < 8; j++) {
                float v = s[i][j] * 0.125f;
                if (needmask) {
                    int qr = m0 + 4 * ty + i;
                    int kc = n0 + 8 * tx + j;
                    if (kc > qr || kc <= qr - WINDOW_SZ) v = -1e30f;
                }
                s[i][j] = v;
            }

#pragma unroll
        for (int i = 0; i < 4; i++) {
            float tmax = s[i][0];
#pragma unroll
            for (int j = 1; j < 8; j++) tmax = fmaxf(tmax, s[i][j]);
#pragma unroll
            for (int off = 4; off > 0; off >>= 1)
                tmax = fmaxf(tmax, __shfl_xor_sync(0xffffffffu, tmax, off));
            float mn = fmaxf(m_i[i], tmax);
            float corr = __expf(m_i[i] - mn);
            m_i[i] = mn;
            float rsum = 0.f;
#pragma unroll
            for (int j = 0; j < 8; j++) {
                float p = __expf(s[i][j] - mn);
                s[i][j] = p;
                rsum += p;
            }
#pragma unroll
            for (int off = 4; off > 0; off >>= 1)
                rsum += __shfl_xor_sync(0xffffffffu, rsum, off);
            l_i[i] = l_i[i] * corr + rsum;
#pragma unroll
            for (int j = 0; j < 8; j++) o[i][j] *= corr;
        }

        __syncthreads();
#pragma unroll
        for (int j = 0; j < 8; j++) {
            int k = 8 * tx + j;
            int ch = ty ^ ((k >> 2) & 15);
            *reinterpret_cast<float4*>(&KP[k * 64 + 4 * ch]) =
                make_float4(s[0][j], s[1][j], s[2][j], s[3][j]);
        }
        __syncthreads();

#pragma unroll 8
        for (int k = 0; k < 64; k++) {
            float4 p4 = *reinterpret_cast<const float4*>(
                &KP[k * 64 + 4 * (ty ^ ((k >> 2) & 15))]);
            float4 v0 = *reinterpret_cast<const float4*>(&Vs[k * 64 + 8 * tx]);
            float4 v1 = *reinterpret_cast<const float4*>(&Vs[k * 64 + 8 * tx + 4]);
            float p[4] = {p4.x, p4.y, p4.z, p4.w};
            float vv[8] = {v0.x, v0.y, v0.z, v0.w, v1.x, v1.y, v1.z, v1.w};
#pragma unroll
            for (int i = 0; i < 4; i++)
#pragma unroll
                for (int j = 0; j < 8; j++) o[i][j] += p[i] * vv[j];
        }
    }

#pragma unroll
    for (int i = 0; i < 4; i++) {
        float inv = 1.f / l_i[i];
        int qr = m0 + 4 * ty + i;
        float4 w0 = make_float4(o[i][0] * inv, o[i][1] * inv, o[i][2] * inv, o[i][3] * inv);
        float4 w1 = make_float4(o[i][4] * inv, o[i][5] * inv, o[i][6] * inv, o[i][7] * inv);
        *reinterpret_cast<float4*>(&y[(size_t)qr * C_DIM + h * HDIM + 8 * tx]) = w0;
        *reinterpret_cast<float4*>(&y[(size_t)qr * C_DIM + h * HDIM + 8 * tx + 4]) = w1;
    }
}

// ---------------------------------------------------------------------------
extern "C" void kernel_launch(void* const* d_in, const int* in_sizes, int n_in,
                              void* d_out, int out_size)
{
    const float* x     = (const float*)d_in[0];
    const float* Wq    = (const float*)d_in[1];
    const float* Wkv   = (const float*)d_in[2];
    const float* Wproj = (const float*)d_in[3];
    float* out = (float*)d_out;

    float *gq, *gkv, *gy;
    cudaGetSymbolAddress((void**)&gq, g_q);
    cudaGetSymbolAddress((void**)&gkv, g_kv);
    cudaGetSymbolAddress((void**)&gy, g_y);

    __nv_bfloat16 *xh, *xl, *wqh, *wql, *wkh, *wkl, *wph, *wpl, *yh, *yl;
    cudaGetSymbolAddress((void**)&xh, g_xh);   cudaGetSymbolAddress((void**)&xl, g_xl);
    cudaGetSymbolAddress((void**)&wqh, g_wqh); cudaGetSymbolAddress((void**)&wql, g_wql);
    cudaGetSymbolAddress((void**)&wkh, g_wkh); cudaGetSymbolAddress((void**)&wkl, g_wkl);
    cudaGetSymbolAddress((void**)&wph, g_wph); cudaGetSymbolAddress((void**)&wpl, g_wpl);
    cudaGetSymbolAddress((void**)&yh, g_yh);   cudaGetSymbolAddress((void**)&yl, g_yl);

    static bool attr_set = false;
    if (!attr_set) {
        cudaFuncSetAttribute(gemm_tc, cudaFuncAttributeMaxDynamicSharedMemorySize,
                             2 * CHUNK_BYTES);
        attr_set = true;
    }

    const int nx4 = T_SEQ * C_DIM / 4;
    const int nq4 = C_DIM * C_DIM / 4;
    const int nk4 = KV_DIM * C_DIM / 4;

    cvt_split<<<(nx4 + 255) / 256, 256>>>(x, xh, xl, nx4);
    cvt_split<<<(nq4 + 255) / 256, 256>>>(Wq, wqh, wql, nq4);
    cvt_split<<<(nk4 + 255) / 256, 256>>>(Wkv, wkh, wkl, nk4);
    cvt_split<<<(nq4 + 255) / 256, 256>>>(Wproj, wph, wpl, nq4);

    // Q = x @ Wq^T   [2048,1024]
    gemm_tc<<<dim3(C_DIM / 128, T_SEQ / 128), 256, 2 * CHUNK_BYTES>>>(
        xh, xl, wqh, wql, gq, C_DIM);
    // KV = x @ Wkv^T [2048,512]
    gemm_tc<<<dim3(KV_DIM / 128, T_SEQ / 128), 256, 2 * CHUNK_BYTES>>>(
        xh, xl, wkh, wkl, gkv, KV_DIM);

    norm_rope_kernel<<<dim3(T_SEQ, HEADS + KV_HEADS), 32>>>(gq, gkv);
    attn_kernel<<<dim3(T_SEQ / 64, HEADS), 128>>>(gq, gkv, gy);

    cvt_split<<<(nx4 + 255) / 256, 256>>>(gy, yh, yl, nx4);
    // out = y @ Wproj^T
    gemm_tc<<<dim3(C_DIM / 128, T_SEQ / 128), 256, 2 * CHUNK_BYTES>>>(
        yh, yl, wph, wpl, out, C_DIM);
}

// round 12
// speedup vs baseline: 3.7589x; 1.6621x over previous
#include <cuda_runtime.h>
#include <cuda_bf16.h>
#include <math.h>

#define T_SEQ 2048
#define C_DIM 1024
#define HEADS 16
#define KV_HEADS 4
#define HDIM 64
#define KV_DIM 512
#define WINDOW_SZ 512

typedef unsigned long long ull;

// ---------------- scratch (no cudaMalloc allowed) ----------------
__device__ float g_q[T_SEQ * C_DIM];
__device__ float g_kv[T_SEQ * KV_DIM];

__device__ __nv_bfloat16 g_xh[T_SEQ * C_DIM], g_xl[T_SEQ * C_DIM];
__device__ __nv_bfloat16 g_wqh[C_DIM * C_DIM], g_wql[C_DIM * C_DIM];
__device__ __nv_bfloat16 g_wkh[KV_DIM * C_DIM], g_wkl[KV_DIM * C_DIM];
__device__ __nv_bfloat16 g_wph[C_DIM * C_DIM], g_wpl[C_DIM * C_DIM];
__device__ __nv_bfloat16 g_yh[T_SEQ * C_DIM], g_yl[T_SEQ * C_DIM];
__device__ __nv_bfloat16 g_qh[T_SEQ * C_DIM], g_ql[T_SEQ * C_DIM];
__device__ __nv_bfloat16 g_kvh[T_SEQ * KV_DIM], g_kvl[T_SEQ * KV_DIM];

// ---------------- PTX helpers (all baseline-arch: sm_80/75 era) ----------------
__device__ __forceinline__ unsigned smem_u32(const void* p) {
    unsigned a;
    asm("{ .reg .u64 t; cvta.to.shared.u64 t, %1; cvt.u32.u64 %0, t; }"
        : "=r"(a) : "l"(p));
    return a;
}
__device__ __forceinline__ void cp_async16(unsigned dst, const void* src) {
    asm volatile("cp.async.cg.shared.global [%0], [%1], 16;\n"
                 :: "r"(dst), "l"(src) : "memory");
}
__device__ __forceinline__ void ldm4(unsigned addr, unsigned& r0, unsigned& r1,
                                     unsigned& r2, unsigned& r3) {
    asm volatile("ldmatrix.sync.aligned.m8n8.x4.shared.b16 {%0,%1,%2,%3}, [%4];"
                 : "=r"(r0), "=r"(r1), "=r"(r2), "=r"(r3) : "r"(addr));
}
__device__ __forceinline__ void ldm4t(unsigned addr, unsigned& r0, unsigned& r1,
                                      unsigned& r2, unsigned& r3) {
    asm volatile("ldmatrix.sync.aligned.m8n8.x4.trans.shared.b16 {%0,%1,%2,%3}, [%4];"
                 : "=r"(r0), "=r"(r1), "=r"(r2), "=r"(r3) : "r"(addr));
}
__device__ __forceinline__ void mma16816(float* c, const unsigned* a,
                                         unsigned b0, unsigned b1) {
    asm volatile("mma.sync.aligned.m16n8k16.row.col.f32.bf16.bf16.f32 "
                 "{%0,%1,%2,%3}, {%4,%5,%6,%7}, {%8,%9}, {%0,%1,%2,%3};"
                 : "+f"(c[0]), "+f"(c[1]), "+f"(c[2]), "+f"(c[3])
                 : "r"(a[0]), "r"(a[1]), "r"(a[2]), "r"(a[3]), "r"(b0), "r"(b1));
}
// pack two floats into bf16x2 (low = x, high = y), plus hi/lo residual split
__device__ __forceinline__ void split2(float x, float y, unsigned& hi, unsigned& lo) {
    __nv_bfloat16 hx = __float2bfloat16(x), hy = __float2bfloat16(y);
    __nv_bfloat16 lx = __float2bfloat16(x - __bfloat162float(hx));
    __nv_bfloat16 ly = __float2bfloat16(y - __bfloat162float(hy));
    hi = (unsigned)__bfloat16_as_ushort(hx) | ((unsigned)__bfloat16_as_ushort(hy) << 16);
    lo = (unsigned)__bfloat16_as_ushort(lx) | ((unsigned)__bfloat16_as_ushort(ly) << 16);
}

// ---------------------------------------------------------------------------
// split-bf16 conversion: hi = bf16(v), lo = bf16(v - hi). Vectorized by 4.
// ---------------------------------------------------------------------------
__global__ void cvt_split(const float* __restrict__ in,
                          __nv_bfloat16* __restrict__ hi,
                          __nv_bfloat16* __restrict__ lo, int n4)
{
    int i = blockIdx.x * blockDim.x + threadIdx.x;
    if (i >= n4) return;
    float4 v = reinterpret_cast<const float4*>(in)[i];
    __nv_bfloat16 h0 = __float2bfloat16(v.x), h1 = __float2bfloat16(v.y);
    __nv_bfloat16 h2 = __float2bfloat16(v.z), h3 = __float2bfloat16(v.w);
    __nv_bfloat16 l0 = __float2bfloat16(v.x - __bfloat162float(h0));
    __nv_bfloat16 l1 = __float2bfloat16(v.y - __bfloat162float(h1));
    __nv_bfloat16 l2 = __float2bfloat16(v.z - __bfloat162float(h2));
    __nv_bfloat16 l3 = __float2bfloat16(v.w - __bfloat162float(h3));
    reinterpret_cast<__nv_bfloat162*>(hi)[2 * i]     = __nv_bfloat162(h0, h1);
    reinterpret_cast<__nv_bfloat162*>(hi)[2 * i + 1] = __nv_bfloat162(h2, h3);
    reinterpret_cast<__nv_bfloat162*>(lo)[2 * i]     = __nv_bfloat162(l0, l1);
    reinterpret_cast<__nv_bfloat162*>(lo)[2 * i + 1] = __nv_bfloat162(l2, l3);
}

// ---------------------------------------------------------------------------
// HMMA split-bf16 GEMM (round-10, passing): C[M,N] = A*B^T.
// ---------------------------------------------------------------------------
#define CHUNK_BYTES 32768

__global__ __launch_bounds__(256)
void gemm_tc(const __nv_bfloat16* __restrict__ Ah, const __nv_bfloat16* __restrict__ Al,
             const __nv_bfloat16* __restrict__ Bh, const __nv_bfloat16* __restrict__ Bl,
             float* __restrict__ C, int Nld)
{
    extern __shared__ __align__(16) unsigned char dsmem[];
    const unsigned sbase = smem_u32(dsmem);

    const int tid = threadIdx.x;
    const int lane = tid & 31, wid = tid >> 5;
    const int m0 = blockIdx.y * 128, n0 = blockIdx.x * 128;
    const int warp_m = (wid & 1) * 64, warp_n = (wid >> 1) * 32;

    const int arow = lane & 15, aoff = lane >> 4;
    const int brow = (lane & 7) + ((lane >> 4) << 3);
    const int boff = (lane >> 3) & 1;

    float acc[4][4][4];
#pragma unroll
    for (int mf = 0; mf < 4; mf++)
#pragma unroll
        for (int nf = 0; nf < 4; nf++)
#pragma unroll
            for (int r = 0; r < 4; r++) acc[mf][nf][r] = 0.f;

    auto fill = [&](int kc, unsigned bufbase) {
#pragma unroll
        for (int i = 0; i < 8; i++) {
            int idx = tid + i * 256;
            int tile = idx >> 9;
            int e = idx & 511;
            int r = e >> 2, c = e & 3;
            const __nv_bfloat16* srcb =
                (tile == 0) ? Ah : (tile == 1) ? Al : (tile == 2) ? Bh : Bl;
            int row = ((tile < 2) ? m0 : n0) + r;
            const __nv_bfloat16* src = srcb + (size_t)row * 1024 + kc * 32 + c * 8;
            unsigned dst = bufbase + tile * 8192 + r * 64 + (((c + (r >> 1)) & 3) << 4);
            cp_async16(dst, src);
        }
        asm volatile("cp.async.commit_group;\n" ::: "memory");
    };

    fill(0, sbase);

    for (int kc = 0; kc < 32; kc++) {
        const unsigned cur = sbase + (kc & 1) * CHUNK_BYTES;
        if (kc + 1 < 32) {
            fill(kc + 1, sbase + ((kc + 1) & 1) * CHUNK_BYTES);
            asm volatile("cp.async.wait_group 1;\n" ::: "memory");
        } else {
            asm volatile("cp.async.wait_group 0;\n" ::: "memory");
        }
        __syncthreads();

        const unsigned aH = cur, aL = cur + 8192, bH = cur + 16384, bL = cur + 24576;
#pragma unroll
        for (int ks = 0; ks < 2; ks++) {
            unsigned ah[4][4], al[4][4], bh[2][4], bl[2][4];
#pragma unroll
            for (int mf = 0; mf < 4; mf++) {
                int row = warp_m + mf * 16 + arow;
                int c = ks * 2 + aoff;
                unsigned off = row * 64 + (((c + (row >> 1)) & 3) << 4);
                ldm4(aH + off, ah[mf][0], ah[mf][1], ah[mf][2], ah[mf][3]);
                ldm4(aL + off, al[mf][0], al[mf][1], al[mf][2], al[mf][3]);
            }
#pragma unroll
            for (int p = 0; p < 2; p++) {
                int row = warp_n + p * 16 + brow;
                int c = ks * 2 + boff;
                unsigned off = row * 64 + (((c + (row >> 1)) & 3) << 4);
                ldm4(bH + off, bh[p][0], bh[p][1], bh[p][2], bh[p][3]);
                ldm4(bL + off, bl[p][0], bl[p][1], bl[p][2], bl[p][3]);
            }
#pragma unroll
            for (int mf = 0; mf < 4; mf++)
#pragma unroll
                for (int p = 0; p < 2; p++) {
                    mma16816(acc[mf][2 * p],     ah[mf], bh[p][0], bh[p][1]);
                    mma16816(acc[mf][2 * p],     ah[mf], bl[p][0], bl[p][1]);
                    mma16816(acc[mf][2 * p],     al[mf], bh[p][0], bh[p][1]);
                    mma16816(acc[mf][2 * p + 1], ah[mf], bh[p][2], bh[p][3]);
                    mma16816(acc[mf][2 * p + 1], ah[mf], bl[p][2], bl[p][3]);
                    mma16816(acc[mf][2 * p + 1], al[mf], bh[p][2], bh[p][3]);
                }
        }
        __syncthreads();
    }

#pragma unroll
    for (int mf = 0; mf < 4; mf++)
#pragma unroll
        for (int nf = 0; nf < 4; nf++) {
            int row = m0 + warp_m + mf * 16 + (lane >> 2);
            int col = n0 + warp_n + nf * 8 + (lane & 3) * 2;
            *reinterpret_cast<float2*>(&C[(size_t)row * Nld + col]) =
                make_float2(acc[mf][nf][0], acc[mf][nf][1]);
            *reinterpret_cast<float2*>(&C[(size_t)(row + 8) * Nld + col]) =
                make_float2(acc[mf][nf][2], acc[mf][nf][3]);
        }
}

// ---------------------------------------------------------------------------
// QK L2-normalize + RoPE. One warp per (t, head).
// ---------------------------------------------------------------------------
__global__ void norm_rope_kernel(float* __restrict__ q, float* __restrict__ kvbuf)
{
    const int t = blockIdx.x;
    const int h = blockIdx.y;
    const int lane = threadIdx.x;
    float* base = (h < HEADS)
        ? q + (size_t)t * C_DIM + h * HDIM
        : kvbuf + (size_t)t * KV_DIM + (h - HEADS) * HDIM;

    float a = base[lane];
    float b = base[lane + 32];
    float ss = a * a + b * b;
#pragma unroll
    for (int off = 16; off > 0; off >>= 1)
        ss += __shfl_xor_sync(0xffffffffu, ss, off);
    float inv = 1.f / (sqrtf(ss) + 1e-6f);

    float theta = powf(10000.f, -(float)lane * (1.f / 32.f));
    float ang = (float)t * theta;
    float sv, cv;
    sincosf(ang, &sv, &cv);

    base[lane]      = (a * cv - b * sv) * inv;
    base[lane + 32] = (b * cv + a * sv) * inv;
}

// ---------------------------------------------------------------------------
// HMMA windowed flash attention. 128 thr (4 warps), 64x64 tiles.
// Warp w: q-rows 16w..16w+15, all 64 cols. hi/lo split: hh+hl+lh.
// Q/K: smem [row][d] 128B rows, chunk swizzle c^(r&7), non-trans ldmatrix.
// V: natural [key][d] layout, ldmatrix.x4.trans for B-frags.
// P: c-frag -> a-frag register remap + hi/lo bf16 split (no smem).
// Epilogue writes bf16 hi/lo y directly.
// ---------------------------------------------------------------------------
__global__ __launch_bounds__(128, 2)
void attn_tc(const __nv_bfloat16* __restrict__ qh, const __nv_bfloat16* __restrict__ ql,
             const __nv_bfloat16* __restrict__ kvh, const __nv_bfloat16* __restrict__ kvl,
             __nv_bfloat16* __restrict__ yh, __nv_bfloat16* __restrict__ yl)
{
    __shared__ __align__(16) __nv_bfloat16 sQH[4096], sQL[4096];
    __shared__ __align__(16) __nv_bfloat16 sKH[4096], sKL[4096];
    __shared__ __align__(16) __nv_bfloat16 sVH[4096], sVL[4096];

    const int mt = blockIdx.x, h = blockIdx.y;
    const int kvhead = h >> 2;
    const int m0 = mt * 64;
    const int tid = threadIdx.x, lane = tid & 31, w = tid >> 5;

    const unsigned uQH = smem_u32(sQH), uQL = smem_u32(sQL);
    const unsigned uKH = smem_u32(sKH), uKL = smem_u32(sKL);
    const unsigned uVH = smem_u32(sVH), uVL = smem_u32(sVL);

    // Q fill (hi+lo): 1024 x 16B chunks
#pragma unroll
    for (int i = 0; i < 8; i++) {
        int idx = tid + i * 128;
        int buf = idx >> 9, e = idx & 511;
        int r = e >> 3, c = e & 7;
        const __nv_bfloat16* src =
            (buf ? ql : qh) + (size_t)(m0 + r) * C_DIM + h * HDIM + c * 8;
        unsigned dst = (buf ? uQL : uQH) + r * 128 + (((c ^ (r & 7))) << 4);
        cp_async16(dst, src);
    }

    // per-thread state: rows r0 = m0+16w+(lane>>2), r1 = r0+8
    float o[8][4];
    float m_i[2], l_i[2];
#pragma unroll
    for (int nf = 0; nf < 8; nf++)
#pragma unroll
        for (int r = 0; r < 4; r++) o[nf][r] = 0.f;
    m_i[0] = m_i[1] = -1e30f;
    l_i[0] = l_i[1] = 0.f;

    const int arow = lane & 15, aoff = lane >> 4;
    const int brow = (lane & 7) + ((lane >> 4) << 3);
    const int boff = (lane >> 3) & 1;
    const int vrow = (lane & 7) + (((lane >> 3) & 1) << 3);
    const int voff = lane >> 4;

    const int nstart = (mt >= 8) ? (mt - 8) : 0;
    for (int nt = nstart; nt <= mt; nt++) {
        const int n0 = nt * 64;
        __syncthreads();  // prior-iter K/V reads done

        // K/V fill (hi+lo): 2048 x 16B chunks
#pragma unroll
        for (int i = 0; i < 16; i++) {
            int idx = tid + i * 128;
            int tile = idx >> 9;  // 0:KH 1:KL 2:VH 3:VL
            int e = idx & 511;
            int r = e >> 3, c = e & 7;
            const __nv_bfloat16* base = (tile & 1) ? kvl : kvh;
            int coloff = (tile < 2) ? (kvhead * HDIM) : (256 + kvhead * HDIM);
            const __nv_bfloat16* src = base + (size_t)(n0 + r) * KV_DIM + coloff + c * 8;
            unsigned db = (tile == 0) ? uKH : (tile == 1) ? uKL : (tile == 2) ? uVH : uVL;
            cp_async16(db + r * 128 + (((c ^ (r & 7))) << 4), src);
        }
        asm volatile("cp.async.commit_group;\n" ::: "memory");
        asm volatile("cp.async.wait_group 0;\n" ::: "memory");
        __syncthreads();

        // ---- S = Q K^T (hh + hl + lh) ----
        float s[8][4];
#pragma unroll
        for (int nf = 0; nf < 8; nf++)
#pragma unroll
            for (int r = 0; r < 4; r++) s[nf][r] = 0.f;

#pragma unroll
        for (int ks = 0; ks < 4; ks++) {
            unsigned ah[4], al[4];
            int ar = 16 * w + arow;
            int ac = ks * 2 + aoff;
            unsigned aaddr = ar * 128 + (((ac ^ (ar & 7))) << 4);
            ldm4(uQH + aaddr, ah[0], ah[1], ah[2], ah[3]);
            ldm4(uQL + aaddr, al[0], al[1], al[2], al[3]);
#pragma unroll
            for (int p = 0; p < 4; p++) {
                unsigned bh[4], bl[4];
                int br = p * 16 + brow;
                int bc = ks * 2 + boff;
                unsigned baddr = br * 128 + (((bc ^ (br & 7))) << 4);
                ldm4(uKH + baddr, bh[0], bh[1], bh[2], bh[3]);
                ldm4(uKL + baddr, bl[0], bl[1], bl[2], bl[3]);
                mma16816(s[2 * p],     ah, bh[0], bh[1]);
                mma16816(s[2 * p],     ah, bl[0], bl[1]);
                mma16816(s[2 * p],     al, bh[0], bh[1]);
                mma16816(s[2 * p + 1], ah, bh[2], bh[3]);
                mma16816(s[2 * p + 1], ah, bl[2], bl[3]);
                mma16816(s[2 * p + 1], al, bh[2], bh[3]);
            }
        }

        // ---- scale + mask ----
        const bool needmask = (nt == mt) || (nt == mt - 8);
        const int r0 = m0 + 16 * w + (lane >> 2);
        const int cbase = n0 + 2 * (lane & 3);
#pragma unroll
        for (int nf = 0; nf < 8; nf++)
#pragma unroll
            for (int r = 0; r < 4; r++) {
                float v = s[nf][r] * 0.125f;
                if (needmask) {
                    int qr = r0 + 8 * (r >> 1);
                    int kc = cbase + 8 * nf + (r & 1);
                    if (kc > qr || kc <= qr - WINDOW_SZ) v = -1e30f;
                }
                s[nf][r] = v;
            }

        // ---- online softmax (rows owned by 4-lane groups) ----
#pragma unroll
        for (int j = 0; j < 2; j++) {
            float tmax = -1e30f;
#pragma unroll
            for (int nf = 0; nf < 8; nf++)
                tmax = fmaxf(tmax, fmaxf(s[nf][2 * j], s[nf][2 * j + 1]));
            tmax = fmaxf(tmax, __shfl_xor_sync(0xffffffffu, tmax, 1));
            tmax = fmaxf(tmax, __shfl_xor_sync(0xffffffffu, tmax, 2));
            float mn = fmaxf(m_i[j], tmax);
            float corr = __expf(m_i[j] - mn);
            m_i[j] = mn;
            float rsum = 0.f;
#pragma unroll
            for (int nf = 0; nf < 8; nf++) {
                float p0 = __expf(s[nf][2 * j] - mn);
                float p1 = __expf(s[nf][2 * j + 1] - mn);
                s[nf][2 * j] = p0;
                s[nf][2 * j + 1] = p1;
                rsum += p0 + p1;
            }
            rsum += __shfl_xor_sync(0xffffffffu, rsum, 1);
            rsum += __shfl_xor_sync(0xffffffffu, rsum, 2);
            l_i[j] = l_i[j] * corr + rsum;
#pragma unroll
            for (int nf = 0; nf < 8; nf++) {
                o[nf][2 * j]     *= corr;
                o[nf][2 * j + 1] *= corr;
            }
        }

        // ---- O += P V : P c-frags -> a-frags (hi/lo), V via ldmatrix.trans ----
#pragma unroll
        for (int kc = 0; kc < 4; kc++) {
            unsigned aph[4], apl[4];
            split2(s[2 * kc][0],     s[2 * kc][1],     aph[0], apl[0]);
            split2(s[2 * kc][2],     s[2 * kc][3],     aph[1], apl[1]);
            split2(s[2 * kc + 1][0], s[2 * kc + 1][1], aph[2], apl[2]);
            split2(s[2 * kc + 1][2], s[2 * kc + 1][3], aph[3], apl[3]);
            int krow = kc * 16 + vrow;
#pragma unroll
            for (int nfb = 0; nfb < 8; nfb += 2) {
                unsigned vh[4], vl[4];
                int chunk = nfb + voff;
                unsigned vaddr = krow * 128 + (((chunk ^ (krow & 7))) << 4);
                ldm4t(uVH + vaddr, vh[0], vh[1], vh[2], vh[3]);
                ldm4t(uVL + vaddr, vl[0], vl[1], vl[2], vl[3]);
                mma16816(o[nfb],     aph, vh[0], vh[1]);
                mma16816(o[nfb],     aph, vl[0], vl[1]);
                mma16816(o[nfb],     apl, vh[0], vh[1]);
                mma16816(o[nfb + 1], aph, vh[2], vh[3]);
                mma16816(o[nfb + 1], aph, vl[2], vl[3]);
                mma16816(o[nfb + 1], apl, vh[2], vh[3]);
            }
        }
    }

    // ---- epilogue: o/l, split to bf16 hi/lo, write y ----
    float inv0 = 1.f / l_i[0], inv1 = 1.f / l_i[1];
#pragma unroll
    for (int nf = 0; nf < 8; nf++) {
        int col = h * HDIM + 8 * nf + 2 * (lane & 3);
#pragma unroll
        for (int j = 0; j < 2; j++) {
            int row = m0 + 16 * w + (lane >> 2) + 8 * j;
            float inv = j ? inv1 : inv0;
            float v0 = o[nf][2 * j] * inv, v1 = o[nf][2 * j + 1] * inv;
            unsigned hi, lo;
            split2(v0, v1, hi, lo);
            *reinterpret_cast<unsigned*>(&yh[(size_t)row * C_DIM + col]) = hi;
            *reinterpret_cast<unsigned*>(&yl[(size_t)row * C_DIM + col]) = lo;
        }
    }
}

// ---------------------------------------------------------------------------
extern "C" void kernel_launch(void* const* d_in, const int* in_sizes, int n_in,
                              void* d_out, int out_size)
{
    const float* x     = (const float*)d_in[0];
    const float* Wq    = (const float*)d_in[1];
    const float* Wkv   = (const float*)d_in[2];
    const float* Wproj = (const float*)d_in[3];
    float* out = (float*)d_out;

    float *gq, *gkv;
    cudaGetSymbolAddress((void**)&gq, g_q);
    cudaGetSymbolAddress((void**)&gkv, g_kv);

    __nv_bfloat16 *xh, *xl, *wqh, *wql, *wkh, *wkl, *wph, *wpl, *yh, *yl;
    __nv_bfloat16 *qh, *ql, *kvh, *kvl;
    cudaGetSymbolAddress((void**)&xh, g_xh);   cudaGetSymbolAddress((void**)&xl, g_xl);
    cudaGetSymbolAddress((void**)&wqh, g_wqh); cudaGetSymbolAddress((void**)&wql, g_wql);
    cudaGetSymbolAddress((void**)&wkh, g_wkh); cudaGetSymbolAddress((void**)&wkl, g_wkl);
    cudaGetSymbolAddress((void**)&wph, g_wph); cudaGetSymbolAddress((void**)&wpl, g_wpl);
    cudaGetSymbolAddress((void**)&yh, g_yh);   cudaGetSymbolAddress((void**)&yl, g_yl);
    cudaGetSymbolAddress((void**)&qh, g_qh);   cudaGetSymbolAddress((void**)&ql, g_ql);
    cudaGetSymbolAddress((void**)&kvh, g_kvh); cudaGetSymbolAddress((void**)&kvl, g_kvl);

    static bool attr_set = false;
    if (!attr_set) {
        cudaFuncSetAttribute(gemm_tc, cudaFuncAttributeMaxDynamicSharedMemorySize,
                             2 * CHUNK_BYTES);
        attr_set = true;
    }

    const int nx4  = T_SEQ * C_DIM / 4;
    const int nq4  = C_DIM * C_DIM / 4;
    const int nk4  = KV_DIM * C_DIM / 4;
    const int nkv4 = T_SEQ * KV_DIM / 4;

    cvt_split<<<(nx4 + 255) / 256, 256>>>(x, xh, xl, nx4);
    cvt_split<<<(nq4 + 255) / 256, 256>>>(Wq, wqh, wql, nq4);
    cvt_split<<<(nk4 + 255) / 256, 256>>>(Wkv, wkh, wkl, nk4);
    cvt_split<<<(nq4 + 255) / 256, 256>>>(Wproj, wph, wpl, nq4);

    // Q = x @ Wq^T ; KV = x @ Wkv^T
    gemm_tc<<<dim3(C_DIM / 128, T_SEQ / 128), 256, 2 * CHUNK_BYTES>>>(
        xh, xl, wqh, wql, gq, C_DIM);
    gemm_tc<<<dim3(KV_DIM / 128, T_SEQ / 128), 256, 2 * CHUNK_BYTES>>>(
        xh, xl, wkh, wkl, gkv, KV_DIM);

    norm_rope_kernel<<<dim3(T_SEQ, HEADS + KV_HEADS), 32>>>(gq, gkv);

    // split normalized/rotated q, kv for tensor-core attention
    cvt_split<<<(nx4 + 255) / 256, 256>>>(gq, qh, ql, nx4);
    cvt_split<<<(nkv4 + 255) / 256, 256>>>(gkv, kvh, kvl, nkv4);

    attn_tc<<<dim3(T_SEQ / 64, HEADS), 128>>>(qh, ql, kvh, kvl, yh, yl);

    // out = y @ Wproj^T
    gemm_tc<<<dim3(C_DIM / 128, T_SEQ / 128), 256, 2 * CHUNK_BYTES>>>(
        yh, yl, wph, wpl, out, C_DIM);
}

// round 13
// speedup vs baseline: 3.8792x; 1.0320x over previous
#include <cuda_runtime.h>
#include <cuda_bf16.h>
#include <math.h>

#define T_SEQ 2048
#define C_DIM 1024
#define HEADS 16
#define KV_HEADS 4
#define HDIM 64
#define KV_DIM 512
#define WINDOW_SZ 512

typedef unsigned long long ull;

// ---------------- scratch (no cudaMalloc allowed) ----------------
__device__ float g_q[T_SEQ * C_DIM];
__device__ float g_kv[T_SEQ * KV_DIM];

__device__ __nv_bfloat16 g_xh[T_SEQ * C_DIM], g_xl[T_SEQ * C_DIM];
__device__ __nv_bfloat16 g_wqh[C_DIM * C_DIM], g_wql[C_DIM * C_DIM];
__device__ __nv_bfloat16 g_wkh[KV_DIM * C_DIM], g_wkl[KV_DIM * C_DIM];
__device__ __nv_bfloat16 g_wph[C_DIM * C_DIM], g_wpl[C_DIM * C_DIM];
__device__ __nv_bfloat16 g_yh[T_SEQ * C_DIM], g_yl[T_SEQ * C_DIM];
__device__ __nv_bfloat16 g_qh[T_SEQ * C_DIM], g_ql[T_SEQ * C_DIM];
__device__ __nv_bfloat16 g_kvh[T_SEQ * KV_DIM], g_kvl[T_SEQ * KV_DIM];

// ---------------- PTX helpers (baseline-arch: sm_80/75 era) ----------------
__device__ __forceinline__ unsigned smem_u32(const void* p) {
    unsigned a;
    asm("{ .reg .u64 t; cvta.to.shared.u64 t, %1; cvt.u32.u64 %0, t; }"
        : "=r"(a) : "l"(p));
    return a;
}
__device__ __forceinline__ void cp_async16(unsigned dst, const void* src) {
    asm volatile("cp.async.cg.shared.global [%0], [%1], 16;\n"
                 :: "r"(dst), "l"(src) : "memory");
}
__device__ __forceinline__ void ldm4(unsigned addr, unsigned& r0, unsigned& r1,
                                     unsigned& r2, unsigned& r3) {
    asm volatile("ldmatrix.sync.aligned.m8n8.x4.shared.b16 {%0,%1,%2,%3}, [%4];"
                 : "=r"(r0), "=r"(r1), "=r"(r2), "=r"(r3) : "r"(addr));
}
__device__ __forceinline__ void ldm4t(unsigned addr, unsigned& r0, unsigned& r1,
                                      unsigned& r2, unsigned& r3) {
    asm volatile("ldmatrix.sync.aligned.m8n8.x4.trans.shared.b16 {%0,%1,%2,%3}, [%4];"
                 : "=r"(r0), "=r"(r1), "=r"(r2), "=r"(r3) : "r"(addr));
}
__device__ __forceinline__ void mma16816(float* c, const unsigned* a,
                                         unsigned b0, unsigned b1) {
    asm volatile("mma.sync.aligned.m16n8k16.row.col.f32.bf16.bf16.f32 "
                 "{%0,%1,%2,%3}, {%4,%5,%6,%7}, {%8,%9}, {%0,%1,%2,%3};"
                 : "+f"(c[0]), "+f"(c[1]), "+f"(c[2]), "+f"(c[3])
                 : "r"(a[0]), "r"(a[1]), "r"(a[2]), "r"(a[3]), "r"(b0), "r"(b1));
}
__device__ __forceinline__ void split2(float x, float y, unsigned& hi, unsigned& lo) {
    __nv_bfloat16 hx = __float2bfloat16(x), hy = __float2bfloat16(y);
    __nv_bfloat16 lx = __float2bfloat16(x - __bfloat162float(hx));
    __nv_bfloat16 ly = __float2bfloat16(y - __bfloat162float(hy));
    hi = (unsigned)__bfloat16_as_ushort(hx) | ((unsigned)__bfloat16_as_ushort(hy) << 16);
    lo = (unsigned)__bfloat16_as_ushort(lx) | ((unsigned)__bfloat16_as_ushort(ly) << 16);
}

// ---------------------------------------------------------------------------
// split-bf16 conversion of x (hi = bf16(v), lo = bf16(v - hi))
// ---------------------------------------------------------------------------
__global__ void cvt_split(const float* __restrict__ in,
                          __nv_bfloat16* __restrict__ hi,
                          __nv_bfloat16* __restrict__ lo, int n4)
{
    int i = blockIdx.x * blockDim.x + threadIdx.x;
    if (i >= n4) return;
    float4 v = reinterpret_cast<const float4*>(in)[i];
    __nv_bfloat16 h0 = __float2bfloat16(v.x), h1 = __float2bfloat16(v.y);
    __nv_bfloat16 h2 = __float2bfloat16(v.z), h3 = __float2bfloat16(v.w);
    __nv_bfloat16 l0 = __float2bfloat16(v.x - __bfloat162float(h0));
    __nv_bfloat16 l1 = __float2bfloat16(v.y - __bfloat162float(h1));
    __nv_bfloat16 l2 = __float2bfloat16(v.z - __bfloat162float(h2));
    __nv_bfloat16 l3 = __float2bfloat16(v.w - __bfloat162float(h3));
    reinterpret_cast<__nv_bfloat162*>(hi)[2 * i]     = __nv_bfloat162(h0, h1);
    reinterpret_cast<__nv_bfloat162*>(hi)[2 * i + 1] = __nv_bfloat162(h2, h3);
    reinterpret_cast<__nv_bfloat162*>(lo)[2 * i]     = __nv_bfloat162(l0, l1);
    reinterpret_cast<__nv_bfloat162*>(lo)[2 * i + 1] = __nv_bfloat162(l2, l3);
}

// combined split of the three weight matrices (one launch)
__global__ void cvt_split3(const float* __restrict__ w0, __nv_bfloat16* h0, __nv_bfloat16* l0, int n0,
                           const float* __restrict__ w1, __nv_bfloat16* h1, __nv_bfloat16* l1, int n1,
                           const float* __restrict__ w2, __nv_bfloat16* h2, __nv_bfloat16* l2, int n2)
{
    int i = blockIdx.x * blockDim.x + threadIdx.x;
    const float* in; __nv_bfloat16 *hi, *lo; int j = i;
    if (j < n0)            { in = w0; hi = h0; lo = l0; }
    else if ((j -= n0) < n1) { in = w1; hi = h1; lo = l1; }
    else if ((j -= n1) < n2) { in = w2; hi = h2; lo = l2; }
    else return;
    float4 v = reinterpret_cast<const float4*>(in)[j];
    __nv_bfloat16 a0 = __float2bfloat16(v.x), a1 = __float2bfloat16(v.y);
    __nv_bfloat16 a2 = __float2bfloat16(v.z), a3 = __float2bfloat16(v.w);
    __nv_bfloat16 b0 = __float2bfloat16(v.x - __bfloat162float(a0));
    __nv_bfloat16 b1 = __float2bfloat16(v.y - __bfloat162float(a1));
    __nv_bfloat16 b2 = __float2bfloat16(v.z - __bfloat162float(a2));
    __nv_bfloat16 b3 = __float2bfloat16(v.w - __bfloat162float(a3));
    reinterpret_cast<__nv_bfloat162*>(hi)[2 * j]     = __nv_bfloat162(a0, a1);
    reinterpret_cast<__nv_bfloat162*>(hi)[2 * j + 1] = __nv_bfloat162(a2, a3);
    reinterpret_cast<__nv_bfloat162*>(lo)[2 * j]     = __nv_bfloat162(b0, b1);
    reinterpret_cast<__nv_bfloat162*>(lo)[2 * j + 1] = __nv_bfloat162(b2, b3);
}

// ---------------------------------------------------------------------------
// HMMA split-bf16 GEMM (round-10/11, passing): C[M,N] = A*B^T.
// ---------------------------------------------------------------------------
#define CHUNK_BYTES 32768

__global__ __launch_bounds__(256)
void gemm_tc(const __nv_bfloat16* __restrict__ Ah, const __nv_bfloat16* __restrict__ Al,
             const __nv_bfloat16* __restrict__ Bh, const __nv_bfloat16* __restrict__ Bl,
             float* __restrict__ C, int Nld)
{
    extern __shared__ __align__(16) unsigned char dsmem[];
    const unsigned sbase = smem_u32(dsmem);

    const int tid = threadIdx.x;
    const int lane = tid & 31, wid = tid >> 5;
    const int m0 = blockIdx.y * 128, n0 = blockIdx.x * 128;
    const int warp_m = (wid & 1) * 64, warp_n = (wid >> 1) * 32;

    const int arow = lane & 15, aoff = lane >> 4;
    const int brow = (lane & 7) + ((lane >> 4) << 3);
    const int boff = (lane >> 3) & 1;

    float acc[4][4][4];
#pragma unroll
    for (int mf = 0; mf < 4; mf++)
#pragma unroll
        for (int nf = 0; nf < 4; nf++)
#pragma unroll
            for (int r = 0; r < 4; r++) acc[mf][nf][r] = 0.f;

    auto fill = [&](int kc, unsigned bufbase) {
#pragma unroll
        for (int i = 0; i < 8; i++) {
            int idx = tid + i * 256;
            int tile = idx >> 9;
            int e = idx & 511;
            int r = e >> 2, c = e & 3;
            const __nv_bfloat16* srcb =
                (tile == 0) ? Ah : (tile == 1) ? Al : (tile == 2) ? Bh : Bl;
            int row = ((tile < 2) ? m0 : n0) + r;
            const __nv_bfloat16* src = srcb + (size_t)row * 1024 + kc * 32 + c * 8;
            unsigned dst = bufbase + tile * 8192 + r * 64 + (((c + (r >> 1)) & 3) << 4);
            cp_async16(dst, src);
        }
        asm volatile("cp.async.commit_group;\n" ::: "memory");
    };

    fill(0, sbase);

    for (int kc = 0; kc < 32; kc++) {
        const unsigned cur = sbase + (kc & 1) * CHUNK_BYTES;
        if (kc + 1 < 32) {
            fill(kc + 1, sbase + ((kc + 1) & 1) * CHUNK_BYTES);
            asm volatile("cp.async.wait_group 1;\n" ::: "memory");
        } else {
            asm volatile("cp.async.wait_group 0;\n" ::: "memory");
        }
        __syncthreads();

        const unsigned aH = cur, aL = cur + 8192, bH = cur + 16384, bL = cur + 24576;
#pragma unroll
        for (int ks = 0; ks < 2; ks++) {
            unsigned ah[4][4], al[4][4], bh[2][4], bl[2][4];
#pragma unroll
            for (int mf = 0; mf < 4; mf++) {
                int row = warp_m + mf * 16 + arow;
                int c = ks * 2 + aoff;
                unsigned off = row * 64 + (((c + (row >> 1)) & 3) << 4);
                ldm4(aH + off, ah[mf][0], ah[mf][1], ah[mf][2], ah[mf][3]);
                ldm4(aL + off, al[mf][0], al[mf][1], al[mf][2], al[mf][3]);
            }
#pragma unroll
            for (int p = 0; p < 2; p++) {
                int row = warp_n + p * 16 + brow;
                int c = ks * 2 + boff;
                unsigned off = row * 64 + (((c + (row >> 1)) & 3) << 4);
                ldm4(bH + off, bh[p][0], bh[p][1], bh[p][2], bh[p][3]);
                ldm4(bL + off, bl[p][0], bl[p][1], bl[p][2], bl[p][3]);
            }
#pragma unroll
            for (int mf = 0; mf < 4; mf++)
#pragma unroll
                for (int p = 0; p < 2; p++) {
                    mma16816(acc[mf][2 * p],     ah[mf], bh[p][0], bh[p][1]);
                    mma16816(acc[mf][2 * p],     ah[mf], bl[p][0], bl[p][1]);
                    mma16816(acc[mf][2 * p],     al[mf], bh[p][0], bh[p][1]);
                    mma16816(acc[mf][2 * p + 1], ah[mf], bh[p][2], bh[p][3]);
                    mma16816(acc[mf][2 * p + 1], ah[mf], bl[p][2], bl[p][3]);
                    mma16816(acc[mf][2 * p + 1], al[mf], bh[p][2], bh[p][3]);
                }
        }
        __syncthreads();
    }

#pragma unroll
    for (int mf = 0; mf < 4; mf++)
#pragma unroll
        for (int nf = 0; nf < 4; nf++) {
            int row = m0 + warp_m + mf * 16 + (lane >> 2);
            int col = n0 + warp_n + nf * 8 + (lane & 3) * 2;
            *reinterpret_cast<float2*>(&C[(size_t)row * Nld + col]) =
                make_float2(acc[mf][nf][0], acc[mf][nf][1]);
            *reinterpret_cast<float2*>(&C[(size_t)(row + 8) * Nld + col]) =
                make_float2(acc[mf][nf][2], acc[mf][nf][3]);
        }
}

// ---------------------------------------------------------------------------
// Fused L2-norm + RoPE + hi/lo split. One warp per (t, unit):
// units 0..15 = Q heads (norm+rope), 16..19 = K heads (norm+rope),
// 20..23 = V heads (plain split). Writes bf16 hi/lo only.
// ---------------------------------------------------------------------------
__global__ void norm_rope_split(const float* __restrict__ q, const float* __restrict__ kv,
                                __nv_bfloat16* __restrict__ qh, __nv_bfloat16* __restrict__ ql,
                                __nv_bfloat16* __restrict__ kvh, __nv_bfloat16* __restrict__ kvl)
{
    const int t = blockIdx.x;
    const int u = blockIdx.y;
    const int lane = threadIdx.x;

    if (u < 20) {  // Q or K: L2 norm + RoPE
        const float* src;
        __nv_bfloat16 *dh, *dl;
        size_t off;
        if (u < HEADS) {
            off = (size_t)t * C_DIM + u * HDIM;
            src = q + off; dh = qh + off; dl = ql + off;
        } else {
            off = (size_t)t * KV_DIM + (u - HEADS) * HDIM;
            src = kv + off; dh = kvh + off; dl = kvl + off;
        }
        float a = src[lane];
        float b = src[lane + 32];
        float ss = a * a + b * b;
#pragma unroll
        for (int o = 16; o > 0; o >>= 1)
            ss += __shfl_xor_sync(0xffffffffu, ss, o);
        float inv = 1.f / (sqrtf(ss) + 1e-6f);

        float theta = powf(10000.f, -(float)lane * (1.f / 32.f));
        float ang = (float)t * theta;
        float sv, cv;
        sincosf(ang, &sv, &cv);

        float v0 = (a * cv - b * sv) * inv;
        float v1 = (b * cv + a * sv) * inv;
        __nv_bfloat16 h0 = __float2bfloat16(v0);
        __nv_bfloat16 h1 = __float2bfloat16(v1);
        dh[lane]      = h0;
        dh[lane + 32] = h1;
        dl[lane]      = __float2bfloat16(v0 - __bfloat162float(h0));
        dl[lane + 32] = __float2bfloat16(v1 - __bfloat162float(h1));
    } else {  // V: plain split
        size_t off = (size_t)t * KV_DIM + 256 + (u - 20) * HDIM;
        const float* src = kv + off;
#pragma unroll
        for (int j = 0; j < 2; j++) {
            float v = src[lane + 32 * j];
            __nv_bfloat16 hh = __float2bfloat16(v);
            kvh[off + lane + 32 * j] = hh;
            kvl[off + lane + 32 * j] = __float2bfloat16(v - __bfloat162float(hh));
        }
    }
}

// ---------------------------------------------------------------------------
// HMMA windowed flash attention, double-buffered K/V.
// 128 thr (4 warps), 64x64 tiles; Q static smem, K/V 2-stage dynamic ring.
// ---------------------------------------------------------------------------
#define KV_STAGE_BYTES 32768   // KH|KL|VH|VL x 8KB

__global__ __launch_bounds__(128, 2)
void attn_tc(const __nv_bfloat16* __restrict__ qh, const __nv_bfloat16* __restrict__ ql,
             const __nv_bfloat16* __restrict__ kvh, const __nv_bfloat16* __restrict__ kvl,
             __nv_bfloat16* __restrict__ yh, __nv_bfloat16* __restrict__ yl)
{
    __shared__ __align__(16) __nv_bfloat16 sQH[4096], sQL[4096];
    extern __shared__ __align__(16) unsigned char kvsmem[];
    const unsigned kvbase = smem_u32(kvsmem);

    const int mt = blockIdx.x, h = blockIdx.y;
    const int kvhead = h >> 2;
    const int m0 = mt * 64;
    const int tid = threadIdx.x, lane = tid & 31, w = tid >> 5;

    const unsigned uQH = smem_u32(sQH), uQL = smem_u32(sQL);

    // Q fill (hi+lo): 1024 x 16B chunks (part of first commit group)
#pragma unroll
    for (int i = 0; i < 8; i++) {
        int idx = tid + i * 128;
        int buf = idx >> 9, e = idx & 511;
        int r = e >> 3, c = e & 7;
        const __nv_bfloat16* src =
            (buf ? ql : qh) + (size_t)(m0 + r) * C_DIM + h * HDIM + c * 8;
        unsigned dst = (buf ? uQL : uQH) + r * 128 + (((c ^ (r & 7))) << 4);
        cp_async16(dst, src);
    }

    auto fill_kv = [&](int nt, unsigned bufbase) {
        const int n0 = nt * 64;
#pragma unroll
        for (int i = 0; i < 16; i++) {
            int idx = tid + i * 128;
            int tile = idx >> 9;  // 0:KH 1:KL 2:VH 3:VL
            int e = idx & 511;
            int r = e >> 3, c = e & 7;
            const __nv_bfloat16* base = (tile & 1) ? kvl : kvh;
            int coloff = (tile < 2) ? (kvhead * HDIM) : (256 + kvhead * HDIM);
            const __nv_bfloat16* src = base + (size_t)(n0 + r) * KV_DIM + coloff + c * 8;
            cp_async16(bufbase + tile * 8192 + r * 128 + (((c ^ (r & 7))) << 4), src);
        }
        asm volatile("cp.async.commit_group;\n" ::: "memory");
    };

    float o[8][4];
    float m_i[2], l_i[2];
#pragma unroll
    for (int nf = 0; nf < 8; nf++)
#pragma unroll
        for (int r = 0; r < 4; r++) o[nf][r] = 0.f;
    m_i[0] = m_i[1] = -1e30f;
    l_i[0] = l_i[1] = 0.f;

    const int arow = lane & 15, aoff = lane >> 4;
    const int brow = (lane & 7) + ((lane >> 4) << 3);
    const int boff = (lane >> 3) & 1;
    const int vrow = (lane & 7) + (((lane >> 3) & 1) << 3);
    const int voff = lane >> 4;

    const int nstart = (mt >= 8) ? (mt - 8) : 0;
    fill_kv(nstart, kvbase);   // group 0 (includes Q fill)

    for (int nt = nstart; nt <= mt; nt++) {
        const int n0 = nt * 64;
        const int cb = (nt - nstart) & 1;
        const unsigned cur = kvbase + cb * KV_STAGE_BYTES;

        __syncthreads();   // all warps done with the buffer we're about to refill
        if (nt + 1 <= mt) {
            fill_kv(nt + 1, kvbase + (cb ^ 1) * KV_STAGE_BYTES);
            asm volatile("cp.async.wait_group 1;\n" ::: "memory");
        } else {
            asm volatile("cp.async.wait_group 0;\n" ::: "memory");
        }
        __syncthreads();

        const unsigned uKH = cur, uKL = cur + 8192, uVH = cur + 16384, uVL = cur + 24576;

        // ---- S = Q K^T (hh + hl + lh) ----
        float s[8][4];
#pragma unroll
        for (int nf = 0; nf < 8; nf++)
#pragma unroll
            for (int r = 0; r < 4; r++) s[nf][r] = 0.f;

#pragma unroll
        for (int ks = 0; ks < 4; ks++) {
            unsigned ah[4], al[4];
            int ar = 16 * w + arow;
            int ac = ks * 2 + aoff;
            unsigned aaddr = ar * 128 + (((ac ^ (ar & 7))) << 4);
            ldm4(uQH + aaddr, ah[0], ah[1], ah[2], ah[3]);
            ldm4(uQL + aaddr, al[0], al[1], al[2], al[3]);
#pragma unroll
            for (int p = 0; p < 4; p++) {
                unsigned bh[4], bl[4];
                int br = p * 16 + brow;
                int bc = ks * 2 + boff;
                unsigned baddr = br * 128 + (((bc ^ (br & 7))) << 4);
                ldm4(uKH + baddr, bh[0], bh[1], bh[2], bh[3]);
                ldm4(uKL + baddr, bl[0], bl[1], bl[2], bl[3]);
                mma16816(s[2 * p],     ah, bh[0], bh[1]);
                mma16816(s[2 * p],     ah, bl[0], bl[1]);
                mma16816(s[2 * p],     al, bh[0], bh[1]);
                mma16816(s[2 * p + 1], ah, bh[2], bh[3]);
                mma16816(s[2 * p + 1], ah, bl[2], bl[3]);
                mma16816(s[2 * p + 1], al, bh[2], bh[3]);
            }
        }

        // ---- scale + mask ----
        const bool needmask = (nt == mt) || (nt == mt - 8);
        const int r0 = m0 + 16 * w + (lane >> 2);
        const int cbase = n0 + 2 * (lane & 3);
#pragma unroll
        for (int nf = 0; nf < 8; nf++)
#pragma unroll
            for (int r = 0; r < 4; r++) {
                float v = s[nf][r] * 0.125f;
                if (needmask) {
                    int qr = r0 + 8 * (r >> 1);
                    int kc = cbase + 8 * nf + (r & 1);
                    if (kc > qr || kc <= qr - WINDOW_SZ) v = -1e30f;
                }
                s[nf][r] = v;
            }

        // ---- online softmax ----
#pragma unroll
        for (int j = 0; j < 2; j++) {
            float tmax = -1e30f;
#pragma unroll
            for (int nf = 0; nf < 8; nf++)
                tmax = fmaxf(tmax, fmaxf(s[nf][2 * j], s[nf][2 * j + 1]));
            tmax = fmaxf(tmax, __shfl_xor_sync(0xffffffffu, tmax, 1));
            tmax = fmaxf(tmax, __shfl_xor_sync(0xffffffffu, tmax, 2));
            float mn = fmaxf(m_i[j], tmax);
            float corr = __expf(m_i[j] - mn);
            m_i[j] = mn;
            float rsum = 0.f;
#pragma unroll
            for (int nf = 0; nf < 8; nf++) {
                float p0 = __expf(s[nf][2 * j] - mn);
                float p1 = __expf(s[nf][2 * j + 1] - mn);
                s[nf][2 * j] = p0;
                s[nf][2 * j + 1] = p1;
                rsum += p0 + p1;
            }
            rsum += __shfl_xor_sync(0xffffffffu, rsum, 1);
            rsum += __shfl_xor_sync(0xffffffffu, rsum, 2);
            l_i[j] = l_i[j] * corr + rsum;
#pragma unroll
            for (int nf = 0; nf < 8; nf++) {
                o[nf][2 * j]     *= corr;
                o[nf][2 * j + 1] *= corr;
            }
        }

        // ---- O += P V ----
#pragma unroll
        for (int kc = 0; kc < 4; kc++) {
            unsigned aph[4], apl[4];
            split2(s[2 * kc][0],     s[2 * kc][1],     aph[0], apl[0]);
            split2(s[2 * kc][2],     s[2 * kc][3],     aph[1], apl[1]);
            split2(s[2 * kc + 1][0], s[2 * kc + 1][1], aph[2], apl[2]);
            split2(s[2 * kc + 1][2], s[2 * kc + 1][3], aph[3], apl[3]);
            int krow = kc * 16 + vrow;
#pragma unroll
            for (int nfb = 0; nfb < 8; nfb += 2) {
                unsigned vh[4], vl[4];
                int chunk = nfb + voff;
                unsigned vaddr = krow * 128 + (((chunk ^ (krow & 7))) << 4);
                ldm4t(uVH + vaddr, vh[0], vh[1], vh[2], vh[3]);
                ldm4t(uVL + vaddr, vl[0], vl[1], vl[2], vl[3]);
                mma16816(o[nfb],     aph, vh[0], vh[1]);
                mma16816(o[nfb],     aph, vl[0], vl[1]);
                mma16816(o[nfb],     apl, vh[0], vh[1]);
                mma16816(o[nfb + 1], aph, vh[2], vh[3]);
                mma16816(o[nfb + 1], aph, vl[2], vl[3]);
                mma16816(o[nfb + 1], apl, vh[2], vh[3]);
            }
        }
    }

    // ---- epilogue ----
    float inv0 = 1.f / l_i[0], inv1 = 1.f / l_i[1];
#pragma unroll
    for (int nf = 0; nf < 8; nf++) {
        int col = h * HDIM + 8 * nf + 2 * (lane & 3);
#pragma unroll
        for (int j = 0; j < 2; j++) {
            int row = m0 + 16 * w + (lane >> 2) + 8 * j;
            float inv = j ? inv1 : inv0;
            float v0 = o[nf][2 * j] * inv, v1 = o[nf][2 * j + 1] * inv;
            unsigned hi, lo;
            split2(v0, v1, hi, lo);
            *reinterpret_cast<unsigned*>(&yh[(size_t)row * C_DIM + col]) = hi;
            *reinterpret_cast<unsigned*>(&yl[(size_t)row * C_DIM + col]) = lo;
        }
    }
}

// ---------------------------------------------------------------------------
extern "C" void kernel_launch(void* const* d_in, const int* in_sizes, int n_in,
                              void* d_out, int out_size)
{
    const float* x     = (const float*)d_in[0];
    const float* Wq    = (const float*)d_in[1];
    const float* Wkv   = (const float*)d_in[2];
    const float* Wproj = (const float*)d_in[3];
    float* out = (float*)d_out;

    float *gq, *gkv;
    cudaGetSymbolAddress((void**)&gq, g_q);
    cudaGetSymbolAddress((void**)&gkv, g_kv);

    __nv_bfloat16 *xh, *xl, *wqh, *wql, *wkh, *wkl, *wph, *wpl, *yh, *yl;
    __nv_bfloat16 *qh, *ql, *kvh, *kvl;
    cudaGetSymbolAddress((void**)&xh, g_xh);   cudaGetSymbolAddress((void**)&xl, g_xl);
    cudaGetSymbolAddress((void**)&wqh, g_wqh); cudaGetSymbolAddress((void**)&wql, g_wql);
    cudaGetSymbolAddress((void**)&wkh, g_wkh); cudaGetSymbolAddress((void**)&wkl, g_wkl);
    cudaGetSymbolAddress((void**)&wph, g_wph); cudaGetSymbolAddress((void**)&wpl, g_wpl);
    cudaGetSymbolAddress((void**)&yh, g_yh);   cudaGetSymbolAddress((void**)&yl, g_yl);
    cudaGetSymbolAddress((void**)&qh, g_qh);   cudaGetSymbolAddress((void**)&ql, g_ql);
    cudaGetSymbolAddress((void**)&kvh, g_kvh); cudaGetSymbolAddress((void**)&kvl, g_kvl);

    static bool attr_set = false;
    if (!attr_set) {
        cudaFuncSetAttribute(gemm_tc, cudaFuncAttributeMaxDynamicSharedMemorySize,
                             2 * CHUNK_BYTES);
        cudaFuncSetAttribute(attn_tc, cudaFuncAttributeMaxDynamicSharedMemorySize,
                             2 * KV_STAGE_BYTES);
        attr_set = true;
    }

    const int nx4 = T_SEQ * C_DIM / 4;
    const int nq4 = C_DIM * C_DIM / 4;
    const int nk4 = KV_DIM * C_DIM / 4;
    const int nw4 = 2 * nq4 + nk4;

    cvt_split<<<(nx4 + 255) / 256, 256>>>(x, xh, xl, nx4);
    cvt_split3<<<(nw4 + 255) / 256, 256>>>(Wq, wqh, wql, nq4,
                                           Wkv, wkh, wkl, nk4,
                                           Wproj, wph, wpl, nq4);

    // Q = x @ Wq^T ; KV = x @ Wkv^T
    gemm_tc<<<dim3(C_DIM / 128, T_SEQ / 128), 256, 2 * CHUNK_BYTES>>>(
        xh, xl, wqh, wql, gq, C_DIM);
    gemm_tc<<<dim3(KV_DIM / 128, T_SEQ / 128), 256, 2 * CHUNK_BYTES>>>(
        xh, xl, wkh, wkl, gkv, KV_DIM);

    // fused norm + rope + bf16 hi/lo split
    norm_rope_split<<<dim3(T_SEQ, HEADS + 2 * KV_HEADS), 32>>>(
        gq, gkv, qh, ql, kvh, kvl);

    attn_tc<<<dim3(T_SEQ / 64, HEADS), 128, 2 * KV_STAGE_BYTES>>>(
        qh, ql, kvh, kvl, yh, yl);

    // out = y @ Wproj^T
    gemm_tc<<<dim3(C_DIM / 128, T_SEQ / 128), 256, 2 * CHUNK_BYTES>>>(
        yh, yl, wph, wpl, out, C_DIM);
}

// round 14
// speedup vs baseline: 4.1022x; 1.0575x over previous
#include <cuda_runtime.h>
#include <cuda_bf16.h>
#include <math.h>

#define T_SEQ 2048
#define C_DIM 1024
#define HEADS 16
#define KV_HEADS 4
#define HDIM 64
#define KV_DIM 512
#define WINDOW_SZ 512

typedef unsigned long long ull;

// ---------------- scratch (no cudaMalloc allowed) ----------------
__device__ float g_q[T_SEQ * C_DIM];
__device__ float g_kv[T_SEQ * KV_DIM];

__device__ __nv_bfloat16 g_xh[T_SEQ * C_DIM], g_xl[T_SEQ * C_DIM];
// Wq (1024 rows) and Wkv (512 rows) concatenated: [1536 x 1024]
__device__ __nv_bfloat16 g_wqkh[1536 * C_DIM], g_wqkl[1536 * C_DIM];
__device__ __nv_bfloat16 g_wph[C_DIM * C_DIM], g_wpl[C_DIM * C_DIM];
__device__ __nv_bfloat16 g_yh[T_SEQ * C_DIM], g_yl[T_SEQ * C_DIM];
__device__ __nv_bfloat16 g_qh[T_SEQ * C_DIM], g_ql[T_SEQ * C_DIM];
__device__ __nv_bfloat16 g_kvh[T_SEQ * KV_DIM], g_kvl[T_SEQ * KV_DIM];

// ---------------- PTX helpers (baseline-arch: sm_80/75 era) ----------------
__device__ __forceinline__ unsigned smem_u32(const void* p) {
    unsigned a;
    asm("{ .reg .u64 t; cvta.to.shared.u64 t, %1; cvt.u32.u64 %0, t; }"
        : "=r"(a) : "l"(p));
    return a;
}
__device__ __forceinline__ void cp_async16(unsigned dst, const void* src) {
    asm volatile("cp.async.cg.shared.global [%0], [%1], 16;\n"
                 :: "r"(dst), "l"(src) : "memory");
}
__device__ __forceinline__ void ldm4(unsigned addr, unsigned& r0, unsigned& r1,
                                     unsigned& r2, unsigned& r3) {
    asm volatile("ldmatrix.sync.aligned.m8n8.x4.shared.b16 {%0,%1,%2,%3}, [%4];"
                 : "=r"(r0), "=r"(r1), "=r"(r2), "=r"(r3) : "r"(addr));
}
__device__ __forceinline__ void ldm4t(unsigned addr, unsigned& r0, unsigned& r1,
                                      unsigned& r2, unsigned& r3) {
    asm volatile("ldmatrix.sync.aligned.m8n8.x4.trans.shared.b16 {%0,%1,%2,%3}, [%4];"
                 : "=r"(r0), "=r"(r1), "=r"(r2), "=r"(r3) : "r"(addr));
}
__device__ __forceinline__ void mma16816(float* c, const unsigned* a,
                                         unsigned b0, unsigned b1) {
    asm volatile("mma.sync.aligned.m16n8k16.row.col.f32.bf16.bf16.f32 "
                 "{%0,%1,%2,%3}, {%4,%5,%6,%7}, {%8,%9}, {%0,%1,%2,%3};"
                 : "+f"(c[0]), "+f"(c[1]), "+f"(c[2]), "+f"(c[3])
                 : "r"(a[0]), "r"(a[1]), "r"(a[2]), "r"(a[3]), "r"(b0), "r"(b1));
}
__device__ __forceinline__ void split2(float x, float y, unsigned& hi, unsigned& lo) {
    __nv_bfloat16 hx = __float2bfloat16(x), hy = __float2bfloat16(y);
    __nv_bfloat16 lx = __float2bfloat16(x - __bfloat162float(hx));
    __nv_bfloat16 ly = __float2bfloat16(y - __bfloat162float(hy));
    hi = (unsigned)__bfloat16_as_ushort(hx) | ((unsigned)__bfloat16_as_ushort(hy) << 16);
    lo = (unsigned)__bfloat16_as_ushort(lx) | ((unsigned)__bfloat16_as_ushort(ly) << 16);
}

// ---------------------------------------------------------------------------
// split-bf16 conversion of x (hi = bf16(v), lo = bf16(v - hi))
// ---------------------------------------------------------------------------
__global__ void cvt_split(const float* __restrict__ in,
                          __nv_bfloat16* __restrict__ hi,
                          __nv_bfloat16* __restrict__ lo, int n4)
{
    int i = blockIdx.x * blockDim.x + threadIdx.x;
    if (i >= n4) return;
    float4 v = reinterpret_cast<const float4*>(in)[i];
    __nv_bfloat16 h0 = __float2bfloat16(v.x), h1 = __float2bfloat16(v.y);
    __nv_bfloat16 h2 = __float2bfloat16(v.z), h3 = __float2bfloat16(v.w);
    __nv_bfloat16 l0 = __float2bfloat16(v.x - __bfloat162float(h0));
    __nv_bfloat16 l1 = __float2bfloat16(v.y - __bfloat162float(h1));
    __nv_bfloat16 l2 = __float2bfloat16(v.z - __bfloat162float(h2));
    __nv_bfloat16 l3 = __float2bfloat16(v.w - __bfloat162float(h3));
    reinterpret_cast<__nv_bfloat162*>(hi)[2 * i]     = __nv_bfloat162(h0, h1);
    reinterpret_cast<__nv_bfloat162*>(hi)[2 * i + 1] = __nv_bfloat162(h2, h3);
    reinterpret_cast<__nv_bfloat162*>(lo)[2 * i]     = __nv_bfloat162(l0, l1);
    reinterpret_cast<__nv_bfloat162*>(lo)[2 * i + 1] = __nv_bfloat162(l2, l3);
}

// combined split of the three weight matrices (one launch):
// Wq -> wqk[0:1024), Wkv -> wqk[1024:1536), Wproj separate.
__global__ void cvt_split3(const float* __restrict__ w0, __nv_bfloat16* h0, __nv_bfloat16* l0, int n0,
                           const float* __restrict__ w1, __nv_bfloat16* h1, __nv_bfloat16* l1, int n1,
                           const float* __restrict__ w2, __nv_bfloat16* h2, __nv_bfloat16* l2, int n2)
{
    int i = blockIdx.x * blockDim.x + threadIdx.x;
    const float* in; __nv_bfloat16 *hi, *lo; int j = i;
    if (j < n0)            { in = w0; hi = h0; lo = l0; }
    else if ((j -= n0) < n1) { in = w1; hi = h1; lo = l1; }
    else if ((j -= n1) < n2) { in = w2; hi = h2; lo = l2; }
    else return;
    float4 v = reinterpret_cast<const float4*>(in)[j];
    __nv_bfloat16 a0 = __float2bfloat16(v.x), a1 = __float2bfloat16(v.y);
    __nv_bfloat16 a2 = __float2bfloat16(v.z), a3 = __float2bfloat16(v.w);
    __nv_bfloat16 b0 = __float2bfloat16(v.x - __bfloat162float(a0));
    __nv_bfloat16 b1 = __float2bfloat16(v.y - __bfloat162float(a1));
    __nv_bfloat16 b2 = __float2bfloat16(v.z - __bfloat162float(a2));
    __nv_bfloat16 b3 = __float2bfloat16(v.w - __bfloat162float(a3));
    reinterpret_cast<__nv_bfloat162*>(hi)[2 * j]     = __nv_bfloat162(a0, a1);
    reinterpret_cast<__nv_bfloat162*>(hi)[2 * j + 1] = __nv_bfloat162(a2, a3);
    reinterpret_cast<__nv_bfloat162*>(lo)[2 * j]     = __nv_bfloat162(b0, b1);
    reinterpret_cast<__nv_bfloat162*>(lo)[2 * j + 1] = __nv_bfloat162(b2, b3);
}

// ---------------------------------------------------------------------------
// HMMA split-bf16 GEMM: C[M,N] = A*B^T. Output split: tiles with n0 < nsplit
// go to C0 (ld Nld0), others to C1 at col n0-nsplit (ld Nld1).
// __launch_bounds__(256, 2): 2 CTAs/SM to hide ldmatrix->MMA latency.
// ---------------------------------------------------------------------------
#define CHUNK_BYTES 32768

__global__ __launch_bounds__(256, 2)
void gemm_tc(const __nv_bfloat16* __restrict__ Ah, const __nv_bfloat16* __restrict__ Al,
             const __nv_bfloat16* __restrict__ Bh, const __nv_bfloat16* __restrict__ Bl,
             float* __restrict__ C0, float* __restrict__ C1,
             int nsplit, int Nld0, int Nld1)
{
    extern __shared__ __align__(16) unsigned char dsmem[];
    const unsigned sbase = smem_u32(dsmem);

    const int tid = threadIdx.x;
    const int lane = tid & 31, wid = tid >> 5;
    const int m0 = blockIdx.y * 128, n0 = blockIdx.x * 128;
    const int warp_m = (wid & 1) * 64, warp_n = (wid >> 1) * 32;

    const int arow = lane & 15, aoff = lane >> 4;
    const int brow = (lane & 7) + ((lane >> 4) << 3);
    const int boff = (lane >> 3) & 1;

    float acc[4][4][4];
#pragma unroll
    for (int mf = 0; mf < 4; mf++)
#pragma unroll
        for (int nf = 0; nf < 4; nf++)
#pragma unroll
            for (int r = 0; r < 4; r++) acc[mf][nf][r] = 0.f;

    auto fill = [&](int kc, unsigned bufbase) {
#pragma unroll
        for (int i = 0; i < 8; i++) {
            int idx = tid + i * 256;
            int tile = idx >> 9;
            int e = idx & 511;
            int r = e >> 2, c = e & 3;
            const __nv_bfloat16* srcb =
                (tile == 0) ? Ah : (tile == 1) ? Al : (tile == 2) ? Bh : Bl;
            int row = ((tile < 2) ? m0 : n0) + r;
            const __nv_bfloat16* src = srcb + (size_t)row * 1024 + kc * 32 + c * 8;
            unsigned dst = bufbase + tile * 8192 + r * 64 + (((c + (r >> 1)) & 3) << 4);
            cp_async16(dst, src);
        }
        asm volatile("cp.async.commit_group;\n" ::: "memory");
    };

    fill(0, sbase);

    for (int kc = 0; kc < 32; kc++) {
        const unsigned cur = sbase + (kc & 1) * CHUNK_BYTES;
        if (kc + 1 < 32) {
            fill(kc + 1, sbase + ((kc + 1) & 1) * CHUNK_BYTES);
            asm volatile("cp.async.wait_group 1;\n" ::: "memory");
        } else {
            asm volatile("cp.async.wait_group 0;\n" ::: "memory");
        }
        __syncthreads();

        const unsigned aH = cur, aL = cur + 8192, bH = cur + 16384, bL = cur + 24576;
#pragma unroll
        for (int ks = 0; ks < 2; ks++) {
            unsigned ah[4][4], al[4][4], bh[2][4], bl[2][4];
#pragma unroll
            for (int mf = 0; mf < 4; mf++) {
                int row = warp_m + mf * 16 + arow;
                int c = ks * 2 + aoff;
                unsigned off = row * 64 + (((c + (row >> 1)) & 3) << 4);
                ldm4(aH + off, ah[mf][0], ah[mf][1], ah[mf][2], ah[mf][3]);
                ldm4(aL + off, al[mf][0], al[mf][1], al[mf][2], al[mf][3]);
            }
#pragma unroll
            for (int p = 0; p < 2; p++) {
                int row = warp_n + p * 16 + brow;
                int c = ks * 2 + boff;
                unsigned off = row * 64 + (((c + (row >> 1)) & 3) << 4);
                ldm4(bH + off, bh[p][0], bh[p][1], bh[p][2], bh[p][3]);
                ldm4(bL + off, bl[p][0], bl[p][1], bl[p][2], bl[p][3]);
            }
#pragma unroll
            for (int mf = 0; mf < 4; mf++)
#pragma unroll
                for (int p = 0; p < 2; p++) {
                    mma16816(acc[mf][2 * p],     ah[mf], bh[p][0], bh[p][1]);
                    mma16816(acc[mf][2 * p],     ah[mf], bl[p][0], bl[p][1]);
                    mma16816(acc[mf][2 * p],     al[mf], bh[p][0], bh[p][1]);
                    mma16816(acc[mf][2 * p + 1], ah[mf], bh[p][2], bh[p][3]);
                    mma16816(acc[mf][2 * p + 1], ah[mf], bl[p][2], bl[p][3]);
                    mma16816(acc[mf][2 * p + 1], al[mf], bh[p][2], bh[p][3]);
                }
        }
        __syncthreads();
    }

    float* Cb; int Nld, coff;
    if (n0 < nsplit) { Cb = C0; Nld = Nld0; coff = n0; }
    else             { Cb = C1; Nld = Nld1; coff = n0 - nsplit; }

#pragma unroll
    for (int mf = 0; mf < 4; mf++)
#pragma unroll
        for (int nf = 0; nf < 4; nf++) {
            int row = m0 + warp_m + mf * 16 + (lane >> 2);
            int col = coff + warp_n + nf * 8 + (lane & 3) * 2;
            *reinterpret_cast<float2*>(&Cb[(size_t)row * Nld + col]) =
                make_float2(acc[mf][nf][0], acc[mf][nf][1]);
            *reinterpret_cast<float2*>(&Cb[(size_t)(row + 8) * Nld + col]) =
                make_float2(acc[mf][nf][2], acc[mf][nf][3]);
        }
}

// ---------------------------------------------------------------------------
// Fused L2-norm + RoPE + hi/lo split. One warp per (t, unit).
// ---------------------------------------------------------------------------
__global__ void norm_rope_split(const float* __restrict__ q, const float* __restrict__ kv,
                                __nv_bfloat16* __restrict__ qh, __nv_bfloat16* __restrict__ ql,
                                __nv_bfloat16* __restrict__ kvh, __nv_bfloat16* __restrict__ kvl)
{
    const int t = blockIdx.x;
    const int u = blockIdx.y;
    const int lane = threadIdx.x;

    if (u < 20) {
        const float* src;
        __nv_bfloat16 *dh, *dl;
        size_t off;
        if (u < HEADS) {
            off = (size_t)t * C_DIM + u * HDIM;
            src = q + off; dh = qh + off; dl = ql + off;
        } else {
            off = (size_t)t * KV_DIM + (u - HEADS) * HDIM;
            src = kv + off; dh = kvh + off; dl = kvl + off;
        }
        float a = src[lane];
        float b = src[lane + 32];
        float ss = a * a + b * b;
#pragma unroll
        for (int o = 16; o > 0; o >>= 1)
            ss += __shfl_xor_sync(0xffffffffu, ss, o);
        float inv = 1.f / (sqrtf(ss) + 1e-6f);

        float theta = powf(10000.f, -(float)lane * (1.f / 32.f));
        float ang = (float)t * theta;
        float sv, cv;
        sincosf(ang, &sv, &cv);

        float v0 = (a * cv - b * sv) * inv;
        float v1 = (b * cv + a * sv) * inv;
        __nv_bfloat16 h0 = __float2bfloat16(v0);
        __nv_bfloat16 h1 = __float2bfloat16(v1);
        dh[lane]      = h0;
        dh[lane + 32] = h1;
        dl[lane]      = __float2bfloat16(v0 - __bfloat162float(h0));
        dl[lane + 32] = __float2bfloat16(v1 - __bfloat162float(h1));
    } else {
        size_t off = (size_t)t * KV_DIM + 256 + (u - 20) * HDIM;
        const float* src = kv + off;
#pragma unroll
        for (int j = 0; j < 2; j++) {
            float v = src[lane + 32 * j];
            __nv_bfloat16 hh = __float2bfloat16(v);
            kvh[off + lane + 32 * j] = hh;
            kvl[off + lane + 32 * j] = __float2bfloat16(v - __bfloat162float(hh));
        }
    }
}

// ---------------------------------------------------------------------------
// HMMA windowed flash attention, double-buffered K/V. (round-12, passing)
// ---------------------------------------------------------------------------
#define KV_STAGE_BYTES 32768

__global__ __launch_bounds__(128, 2)
void attn_tc(const __nv_bfloat16* __restrict__ qh, const __nv_bfloat16* __restrict__ ql,
             const __nv_bfloat16* __restrict__ kvh, const __nv_bfloat16* __restrict__ kvl,
             __nv_bfloat16* __restrict__ yh, __nv_bfloat16* __restrict__ yl)
{
    __shared__ __align__(16) __nv_bfloat16 sQH[4096], sQL[4096];
    extern __shared__ __align__(16) unsigned char kvsmem[];
    const unsigned kvbase = smem_u32(kvsmem);

    const int mt = blockIdx.x, h = blockIdx.y;
    const int kvhead = h >> 2;
    const int m0 = mt * 64;
    const int tid = threadIdx.x, lane = tid & 31, w = tid >> 5;

    const unsigned uQH = smem_u32(sQH), uQL = smem_u32(sQL);

#pragma unroll
    for (int i = 0; i < 8; i++) {
        int idx = tid + i * 128;
        int buf = idx >> 9, e = idx & 511;
        int r = e >> 3, c = e & 7;
        const __nv_bfloat16* src =
            (buf ? ql : qh) + (size_t)(m0 + r) * C_DIM + h * HDIM + c * 8;
        unsigned dst = (buf ? uQL : uQH) + r * 128 + (((c ^ (r & 7))) << 4);
        cp_async16(dst, src);
    }

    auto fill_kv = [&](int nt, unsigned bufbase) {
        const int n0 = nt * 64;
#pragma unroll
        for (int i = 0; i < 16; i++) {
            int idx = tid + i * 128;
            int tile = idx >> 9;
            int e = idx & 511;
            int r = e >> 3, c = e & 7;
            const __nv_bfloat16* base = (tile & 1) ? kvl : kvh;
            int coloff = (tile < 2) ? (kvhead * HDIM) : (256 + kvhead * HDIM);
            const __nv_bfloat16* src = base + (size_t)(n0 + r) * KV_DIM + coloff + c * 8;
            cp_async16(bufbase + tile * 8192 + r * 128 + (((c ^ (r & 7))) << 4), src);
        }
        asm volatile("cp.async.commit_group;\n" ::: "memory");
    };

    float o[8][4];
    float m_i[2], l_i[2];
#pragma unroll
    for (int nf = 0; nf < 8; nf++)
#pragma unroll
        for (int r = 0; r < 4; r++) o[nf][r] = 0.f;
    m_i[0] = m_i[1] = -1e30f;
    l_i[0] = l_i[1] = 0.f;

    const int arow = lane & 15, aoff = lane >> 4;
    const int brow = (lane & 7) + ((lane >> 4) << 3);
    const int boff = (lane >> 3) & 1;
    const int vrow = (lane & 7) + (((lane >> 3) & 1) << 3);
    const int voff = lane >> 4;

    const int nstart = (mt >= 8) ? (mt - 8) : 0;
    fill_kv(nstart, kvbase);

    for (int nt = nstart; nt <= mt; nt++) {
        const int n0 = nt * 64;
        const int cb = (nt - nstart) & 1;
        const unsigned cur = kvbase + cb * KV_STAGE_BYTES;

        __syncthreads();
        if (nt + 1 <= mt) {
            fill_kv(nt + 1, kvbase + (cb ^ 1) * KV_STAGE_BYTES);
            asm volatile("cp.async.wait_group 1;\n" ::: "memory");
        } else {
            asm volatile("cp.async.wait_group 0;\n" ::: "memory");
        }
        __syncthreads();

        const unsigned uKH = cur, uKL = cur + 8192, uVH = cur + 16384, uVL = cur + 24576;

        float s[8][4];
#pragma unroll
        for (int nf = 0; nf < 8; nf++)
#pragma unroll
            for (int r = 0; r < 4; r++) s[nf][r] = 0.f;

#pragma unroll
        for (int ks = 0; ks < 4; ks++) {
            unsigned ah[4], al[4];
            int ar = 16 * w + arow;
            int ac = ks * 2 + aoff;
            unsigned aaddr = ar * 128 + (((ac ^ (ar & 7))) << 4);
            ldm4(uQH + aaddr, ah[0], ah[1], ah[2], ah[3]);
            ldm4(uQL + aaddr, al[0], al[1], al[2], al[3]);
#pragma unroll
            for (int p = 0; p < 4; p++) {
                unsigned bh[4], bl[4];
                int br = p * 16 + brow;
                int bc = ks * 2 + boff;
                unsigned baddr = br * 128 + (((bc ^ (br & 7))) << 4);
                ldm4(uKH + baddr, bh[0], bh[1], bh[2], bh[3]);
                ldm4(uKL + baddr, bl[0], bl[1], bl[2], bl[3]);
                mma16816(s[2 * p],     ah, bh[0], bh[1]);
                mma16816(s[2 * p],     ah, bl[0], bl[1]);
                mma16816(s[2 * p],     al, bh[0], bh[1]);
                mma16816(s[2 * p + 1], ah, bh[2], bh[3]);
                mma16816(s[2 * p + 1], ah, bl[2], bl[3]);
                mma16816(s[2 * p + 1], al, bh[2], bh[3]);
            }
        }

        const bool needmask = (nt == mt) || (nt == mt - 8);
        const int r0 = m0 + 16 * w + (lane >> 2);
        const int cbase = n0 + 2 * (lane & 3);
#pragma unroll
        for (int nf = 0; nf < 8; nf++)
#pragma unroll
            for (int r = 0; r < 4; r++) {
                float v = s[nf][r] * 0.125f;
                if (needmask) {
                    int qr = r0 + 8 * (r >> 1);
                    int kc = cbase + 8 * nf + (r & 1);
                    if (kc > qr || kc <= qr - WINDOW_SZ) v = -1e30f;
                }
                s[nf][r] = v;
            }

#pragma unroll
        for (int j = 0; j < 2; j++) {
            float tmax = -1e30f;
#pragma unroll
            for (int nf = 0; nf < 8; nf++)
                tmax = fmaxf(tmax, fmaxf(s[nf][2 * j], s[nf][2 * j + 1]));
            tmax = fmaxf(tmax, __shfl_xor_sync(0xffffffffu, tmax, 1));
            tmax = fmaxf(tmax, __shfl_xor_sync(0xffffffffu, tmax, 2));
            float mn = fmaxf(m_i[j], tmax);
            float corr = __expf(m_i[j] - mn);
            m_i[j] = mn;
            float rsum = 0.f;
#pragma unroll
            for (int nf = 0; nf < 8; nf++) {
                float p0 = __expf(s[nf][2 * j] - mn);
                float p1 = __expf(s[nf][2 * j + 1] - mn);
                s[nf][2 * j] = p0;
                s[nf][2 * j + 1] = p1;
                rsum += p0 + p1;
            }
            rsum += __shfl_xor_sync(0xffffffffu, rsum, 1);
            rsum += __shfl_xor_sync(0xffffffffu, rsum, 2);
            l_i[j] = l_i[j] * corr + rsum;
#pragma unroll
            for (int nf = 0; nf < 8; nf++) {
                o[nf][2 * j]     *= corr;
                o[nf][2 * j + 1] *= corr;
            }
        }

#pragma unroll
        for (int kc = 0; kc < 4; kc++) {
            unsigned aph[4], apl[4];
            split2(s[2 * kc][0],     s[2 * kc][1],     aph[0], apl[0]);
            split2(s[2 * kc][2],     s[2 * kc][3],     aph[1], apl[1]);
            split2(s[2 * kc + 1][0], s[2 * kc + 1][1], aph[2], apl[2]);
            split2(s[2 * kc + 1][2], s[2 * kc + 1][3], aph[3], apl[3]);
            int krow = kc * 16 + vrow;
#pragma unroll
            for (int nfb = 0; nfb < 8; nfb += 2) {
                unsigned vh[4], vl[4];
                int chunk = nfb + voff;
                unsigned vaddr = krow * 128 + (((chunk ^ (krow & 7))) << 4);
                ldm4t(uVH + vaddr, vh[0], vh[1], vh[2], vh[3]);
                ldm4t(uVL + vaddr, vl[0], vl[1], vl[2], vl[3]);
                mma16816(o[nfb],     aph, vh[0], vh[1]);
                mma16816(o[nfb],     aph, vl[0], vl[1]);
                mma16816(o[nfb],     apl, vh[0], vh[1]);
                mma16816(o[nfb + 1], aph, vh[2], vh[3]);
                mma16816(o[nfb + 1], aph, vl[2], vl[3]);
                mma16816(o[nfb + 1], apl, vh[2], vh[3]);
            }
        }
    }

    float inv0 = 1.f / l_i[0], inv1 = 1.f / l_i[1];
#pragma unroll
    for (int nf = 0; nf < 8; nf++) {
        int col = h * HDIM + 8 * nf + 2 * (lane & 3);
#pragma unroll
        for (int j = 0; j < 2; j++) {
            int row = m0 + 16 * w + (lane >> 2) + 8 * j;
            float inv = j ? inv1 : inv0;
            float v0 = o[nf][2 * j] * inv, v1 = o[nf][2 * j + 1] * inv;
            unsigned hi, lo;
            split2(v0, v1, hi, lo);
            *reinterpret_cast<unsigned*>(&yh[(size_t)row * C_DIM + col]) = hi;
            *reinterpret_cast<unsigned*>(&yl[(size_t)row * C_DIM + col]) = lo;
        }
    }
}

// ---------------------------------------------------------------------------
extern "C" void kernel_launch(void* const* d_in, const int* in_sizes, int n_in,
                              void* d_out, int out_size)
{
    const float* x     = (const float*)d_in[0];
    const float* Wq    = (const float*)d_in[1];
    const float* Wkv   = (const float*)d_in[2];
    const float* Wproj = (const float*)d_in[3];
    float* out = (float*)d_out;

    float *gq, *gkv;
    cudaGetSymbolAddress((void**)&gq, g_q);
    cudaGetSymbolAddress((void**)&gkv, g_kv);

    __nv_bfloat16 *xh, *xl, *wqkh, *wqkl, *wph, *wpl, *yh, *yl;
    __nv_bfloat16 *qh, *ql, *kvh, *kvl;
    cudaGetSymbolAddress((void**)&xh, g_xh);     cudaGetSymbolAddress((void**)&xl, g_xl);
    cudaGetSymbolAddress((void**)&wqkh, g_wqkh); cudaGetSymbolAddress((void**)&wqkl, g_wqkl);
    cudaGetSymbolAddress((void**)&wph, g_wph);   cudaGetSymbolAddress((void**)&wpl, g_wpl);
    cudaGetSymbolAddress((void**)&yh, g_yh);     cudaGetSymbolAddress((void**)&yl, g_yl);
    cudaGetSymbolAddress((void**)&qh, g_qh);     cudaGetSymbolAddress((void**)&ql, g_ql);
    cudaGetSymbolAddress((void**)&kvh, g_kvh);   cudaGetSymbolAddress((void**)&kvl, g_kvl);

    static bool attr_set = false;
    if (!attr_set) {
        cudaFuncSetAttribute(gemm_tc, cudaFuncAttributeMaxDynamicSharedMemorySize,
                             2 * CHUNK_BYTES);
        cudaFuncSetAttribute(attn_tc, cudaFuncAttributeMaxDynamicSharedMemorySize,
                             2 * KV_STAGE_BYTES);
        attr_set = true;
    }

    const int nx4 = T_SEQ * C_DIM / 4;
    const int nq4 = C_DIM * C_DIM / 4;
    const int nk4 = KV_DIM * C_DIM / 4;
    const int nw4 = 2 * nq4 + nk4;

    cvt_split<<<(nx4 + 255) / 256, 256>>>(x, xh, xl, nx4);
    // Wq -> wqk rows [0,1024), Wkv -> wqk rows [1024,1536), Wproj separate
    cvt_split3<<<(nw4 + 255) / 256, 256>>>(
        Wq, wqkh, wqkl, nq4,
        Wkv, wqkh + (size_t)C_DIM * C_DIM, wqkl + (size_t)C_DIM * C_DIM, nk4,
        Wproj, wph, wpl, nq4);

    // Fused [Q | KV] = x @ [Wq; Wkv]^T : N = 1536, 192 CTAs
    gemm_tc<<<dim3(1536 / 128, T_SEQ / 128), 256, 2 * CHUNK_BYTES>>>(
        xh, xl, wqkh, wqkl, gq, gkv, C_DIM, C_DIM, KV_DIM);

    norm_rope_split<<<dim3(T_SEQ, HEADS + 2 * KV_HEADS), 32>>>(
        gq, gkv, qh, ql, kvh, kvl);

    attn_tc<<<dim3(T_SEQ / 64, HEADS), 128, 2 * KV_STAGE_BYTES>>>(
        qh, ql, kvh, kvl, yh, yl);

    // out = y @ Wproj^T
    gemm_tc<<<dim3(C_DIM / 128, T_SEQ / 128), 256, 2 * CHUNK_BYTES>>>(
        yh, yl, wph, wpl, out, nullptr, 1 << 30, C_DIM, 0);
}

// round 16
// speedup vs baseline: 4.5723x; 1.1146x over previous
#include <cuda_runtime.h>
#include <cuda_bf16.h>
#include <math.h>

#define T_SEQ 2048
#define C_DIM 1024
#define HEADS 16
#define KV_HEADS 4
#define HDIM 64
#define KV_DIM 512
#define WINDOW_SZ 512

typedef unsigned long long ull;

// ---------------- scratch (no cudaMalloc allowed) ----------------
__device__ float g_q[T_SEQ * C_DIM];
__device__ float g_kv[T_SEQ * KV_DIM];

__device__ __nv_bfloat16 g_xh[T_SEQ * C_DIM], g_xl[T_SEQ * C_DIM];
// Wq (1024 rows) and Wkv (512 rows) concatenated: [1536 x 1024]
__device__ __nv_bfloat16 g_wqkh[1536 * C_DIM], g_wqkl[1536 * C_DIM];
__device__ __nv_bfloat16 g_wph[C_DIM * C_DIM], g_wpl[C_DIM * C_DIM];
__device__ __nv_bfloat16 g_yh[T_SEQ * C_DIM], g_yl[T_SEQ * C_DIM];
__device__ __nv_bfloat16 g_qh[T_SEQ * C_DIM], g_ql[T_SEQ * C_DIM];
__device__ __nv_bfloat16 g_kvh[T_SEQ * KV_DIM], g_kvl[T_SEQ * KV_DIM];

// ---------------- PTX helpers (baseline-arch: sm_80/75 era) ----------------
__device__ __forceinline__ unsigned smem_u32(const void* p) {
    unsigned a;
    asm("{ .reg .u64 t; cvta.to.shared.u64 t, %1; cvt.u32.u64 %0, t; }"
        : "=r"(a) : "l"(p));
    return a;
}
__device__ __forceinline__ void cp_async16(unsigned dst, const void* src) {
    asm volatile("cp.async.cg.shared.global [%0], [%1], 16;\n"
                 :: "r"(dst), "l"(src) : "memory");
}
__device__ __forceinline__ void ldm4(unsigned addr, unsigned& r0, unsigned& r1,
                                     unsigned& r2, unsigned& r3) {
    asm volatile("ldmatrix.sync.aligned.m8n8.x4.shared.b16 {%0,%1,%2,%3}, [%4];"
                 : "=r"(r0), "=r"(r1), "=r"(r2), "=r"(r3) : "r"(addr));
}
__device__ __forceinline__ void ldm4t(unsigned addr, unsigned& r0, unsigned& r1,
                                      unsigned& r2, unsigned& r3) {
    asm volatile("ldmatrix.sync.aligned.m8n8.x4.trans.shared.b16 {%0,%1,%2,%3}, [%4];"
                 : "=r"(r0), "=r"(r1), "=r"(r2), "=r"(r3) : "r"(addr));
}
__device__ __forceinline__ void mma16816(float* c, const unsigned* a,
                                         unsigned b0, unsigned b1) {
    asm volatile("mma.sync.aligned.m16n8k16.row.col.f32.bf16.bf16.f32 "
                 "{%0,%1,%2,%3}, {%4,%5,%6,%7}, {%8,%9}, {%0,%1,%2,%3};"
                 : "+f"(c[0]), "+f"(c[1]), "+f"(c[2]), "+f"(c[3])
                 : "r"(a[0]), "r"(a[1]), "r"(a[2]), "r"(a[3]), "r"(b0), "r"(b1));
}
__device__ __forceinline__ void split2(float x, float y, unsigned& hi, unsigned& lo) {
    __nv_bfloat16 hx = __float2bfloat16(x), hy = __float2bfloat16(y);
    __nv_bfloat16 lx = __float2bfloat16(x - __bfloat162float(hx));
    __nv_bfloat16 ly = __float2bfloat16(y - __bfloat162float(hy));
    hi = (unsigned)__bfloat16_as_ushort(hx) | ((unsigned)__bfloat16_as_ushort(hy) << 16);
    lo = (unsigned)__bfloat16_as_ushort(lx) | ((unsigned)__bfloat16_as_ushort(ly) << 16);
}

// ---------------------------------------------------------------------------
// Combined hi/lo split of all four fp32 inputs in ONE launch:
// ranges: x, Wq->wqk[0:1024*1024), Wkv->wqk[1024*1024:...), Wproj.
// ---------------------------------------------------------------------------
__global__ void cvt_split4(const float* __restrict__ s0, __nv_bfloat16* h0, __nv_bfloat16* l0, int n0,
                           const float* __restrict__ s1, __nv_bfloat16* h1, __nv_bfloat16* l1, int n1,
                           const float* __restrict__ s2, __nv_bfloat16* h2, __nv_bfloat16* l2, int n2,
                           const float* __restrict__ s3, __nv_bfloat16* h3, __nv_bfloat16* l3, int n3)
{
    int i = blockIdx.x * blockDim.x + threadIdx.x;
    const float* in; __nv_bfloat16 *hi, *lo; int j = i;
    if (j < n0)              { in = s0; hi = h0; lo = l0; }
    else if ((j -= n0) < n1) { in = s1; hi = h1; lo = l1; }
    else if ((j -= n1) < n2) { in = s2; hi = h2; lo = l2; }
    else if ((j -= n2) < n3) { in = s3; hi = h3; lo = l3; }
    else return;
    float4 v = reinterpret_cast<const float4*>(in)[j];
    __nv_bfloat16 a0 = __float2bfloat16(v.x), a1 = __float2bfloat16(v.y);
    __nv_bfloat16 a2 = __float2bfloat16(v.z), a3 = __float2bfloat16(v.w);
    __nv_bfloat16 b0 = __float2bfloat16(v.x - __bfloat162float(a0));
    __nv_bfloat16 b1 = __float2bfloat16(v.y - __bfloat162float(a1));
    __nv_bfloat16 b2 = __float2bfloat16(v.z - __bfloat162float(a2));
    __nv_bfloat16 b3 = __float2bfloat16(v.w - __bfloat162float(a3));
    reinterpret_cast<__nv_bfloat162*>(hi)[2 * j]     = __nv_bfloat162(a0, a1);
    reinterpret_cast<__nv_bfloat162*>(hi)[2 * j + 1] = __nv_bfloat162(a2, a3);
    reinterpret_cast<__nv_bfloat162*>(lo)[2 * j]     = __nv_bfloat162(b0, b1);
    reinterpret_cast<__nv_bfloat162*>(lo)[2 * j + 1] = __nv_bfloat162(b2, b3);
}

// ---------------------------------------------------------------------------
// HMMA split-bf16 GEMM: C[M,N] = A*B^T. Output split: tiles with n0 < nsplit
// go to C0 (ld Nld0), others to C1 at col n0-nsplit (ld Nld1).
// ---------------------------------------------------------------------------
#define CHUNK_BYTES 32768

__global__ __launch_bounds__(256, 2)
void gemm_tc(const __nv_bfloat16* __restrict__ Ah, const __nv_bfloat16* __restrict__ Al,
             const __nv_bfloat16* __restrict__ Bh, const __nv_bfloat16* __restrict__ Bl,
             float* __restrict__ C0, float* __restrict__ C1,
             int nsplit, int Nld0, int Nld1)
{
    extern __shared__ __align__(16) unsigned char dsmem[];
    const unsigned sbase = smem_u32(dsmem);

    const int tid = threadIdx.x;
    const int lane = tid & 31, wid = tid >> 5;
    const int m0 = blockIdx.y * 128, n0 = blockIdx.x * 128;
    const int warp_m = (wid & 1) * 64, warp_n = (wid >> 1) * 32;

    const int arow = lane & 15, aoff = lane >> 4;
    const int brow = (lane & 7) + ((lane >> 4) << 3);
    const int boff = (lane >> 3) & 1;

    float acc[4][4][4];
#pragma unroll
    for (int mf = 0; mf < 4; mf++)
#pragma unroll
        for (int nf = 0; nf < 4; nf++)
#pragma unroll
            for (int r = 0; r < 4; r++) acc[mf][nf][r] = 0.f;

    auto fill = [&](int kc, unsigned bufbase) {
#pragma unroll
        for (int i = 0; i < 8; i++) {
            int idx = tid + i * 256;
            int tile = idx >> 9;
            int e = idx & 511;
            int r = e >> 2, c = e & 3;
            const __nv_bfloat16* srcb =
                (tile == 0) ? Ah : (tile == 1) ? Al : (tile == 2) ? Bh : Bl;
            int row = ((tile < 2) ? m0 : n0) + r;
            const __nv_bfloat16* src = srcb + (size_t)row * 1024 + kc * 32 + c * 8;
            unsigned dst = bufbase + tile * 8192 + r * 64 + (((c + (r >> 1)) & 3) << 4);
            cp_async16(dst, src);
        }
        asm volatile("cp.async.commit_group;\n" ::: "memory");
    };

    fill(0, sbase);

    for (int kc = 0; kc < 32; kc++) {
        const unsigned cur = sbase + (kc & 1) * CHUNK_BYTES;
        if (kc + 1 < 32) {
            fill(kc + 1, sbase + ((kc + 1) & 1) * CHUNK_BYTES);
            asm volatile("cp.async.wait_group 1;\n" ::: "memory");
        } else {
            asm volatile("cp.async.wait_group 0;\n" ::: "memory");
        }
        __syncthreads();

        const unsigned aH = cur, aL = cur + 8192, bH = cur + 16384, bL = cur + 24576;
#pragma unroll
        for (int ks = 0; ks < 2; ks++) {
            unsigned ah[4][4], al[4][4], bh[2][4], bl[2][4];
#pragma unroll
            for (int mf = 0; mf < 4; mf++) {
                int row = warp_m + mf * 16 + arow;
                int c = ks * 2 + aoff;
                unsigned off = row * 64 + (((c + (row >> 1)) & 3) << 4);
                ldm4(aH + off, ah[mf][0], ah[mf][1], ah[mf][2], ah[mf][3]);
                ldm4(aL + off, al[mf][0], al[mf][1], al[mf][2], al[mf][3]);
            }
#pragma unroll
            for (int p = 0; p < 2; p++) {
                int row = warp_n + p * 16 + brow;
                int c = ks * 2 + boff;
                unsigned off = row * 64 + (((c + (row >> 1)) & 3) << 4);
                ldm4(bH + off, bh[p][0], bh[p][1], bh[p][2], bh[p][3]);
                ldm4(bL + off, bl[p][0], bl[p][1], bl[p][2], bl[p][3]);
            }
#pragma unroll
            for (int mf = 0; mf < 4; mf++)
#pragma unroll
                for (int p = 0; p < 2; p++) {
                    mma16816(acc[mf][2 * p],     ah[mf], bh[p][0], bh[p][1]);
                    mma16816(acc[mf][2 * p],     ah[mf], bl[p][0], bl[p][1]);
                    mma16816(acc[mf][2 * p],     al[mf], bh[p][0], bh[p][1]);
                    mma16816(acc[mf][2 * p + 1], ah[mf], bh[p][2], bh[p][3]);
                    mma16816(acc[mf][2 * p + 1], ah[mf], bl[p][2], bl[p][3]);
                    mma16816(acc[mf][2 * p + 1], al[mf], bh[p][2], bh[p][3]);
                }
        }
        __syncthreads();
    }

    float* Cb; int Nld, coff;
    if (n0 < nsplit) { Cb = C0; Nld = Nld0; coff = n0; }
    else             { Cb = C1; Nld = Nld1; coff = n0 - nsplit; }

#pragma unroll
    for (int mf = 0; mf < 4; mf++)
#pragma unroll
        for (int nf = 0; nf < 4; nf++) {
            int row = m0 + warp_m + mf * 16 + (lane >> 2);
            int col = coff + warp_n + nf * 8 + (lane & 3) * 2;
            *reinterpret_cast<float2*>(&Cb[(size_t)row * Nld + col]) =
                make_float2(acc[mf][nf][0], acc[mf][nf][1]);
            *reinterpret_cast<float2*>(&Cb[(size_t)(row + 8) * Nld + col]) =
                make_float2(acc[mf][nf][2], acc[mf][nf][3]);
        }
}

// ---------------------------------------------------------------------------
// Fused L2-norm + RoPE + hi/lo split. 256 threads = 8 warps per block,
// each warp handles one (t, unit); 32 warp-slots per t (24 used).
// units 0..15 Q (norm+rope), 16..19 K (norm+rope), 20..23 V (plain split).
// ---------------------------------------------------------------------------
__global__ __launch_bounds__(256)
void norm_rope_split(const float* __restrict__ q, const float* __restrict__ kv,
                     __nv_bfloat16* __restrict__ qh, __nv_bfloat16* __restrict__ ql,
                     __nv_bfloat16* __restrict__ kvh, __nv_bfloat16* __restrict__ kvl)
{
    const int gw = blockIdx.x * 8 + (threadIdx.x >> 5);   // global warp id
    const int lane = threadIdx.x & 31;
    const int t = gw >> 5;            // 32 warps per t (24 used)
    const int u = gw & 31;
    if (u >= 24) return;

    if (u < 20) {
        const float* src;
        __nv_bfloat16 *dh, *dl;
        size_t off;
        if (u < HEADS) {
            off = (size_t)t * C_DIM + u * HDIM;
            src = q + off; dh = qh + off; dl = ql + off;
        } else {
            off = (size_t)t * KV_DIM + (u - HEADS) * HDIM;
            src = kv + off; dh = kvh + off; dl = kvl + off;
        }
        float a = src[lane];
        float b = src[lane + 32];
        float ss = a * a + b * b;
#pragma unroll
        for (int o = 16; o > 0; o >>= 1)
            ss += __shfl_xor_sync(0xffffffffu, ss, o);
        float inv = 1.f / (sqrtf(ss) + 1e-6f);

        // theta = 10000^(-lane/32) = 2^(-lane*log2(10000)/32)
        float theta = exp2f(-(float)lane * 0.41524101186092f);
        float ang = (float)t * theta;
        float sv, cv;
        sincosf(ang, &sv, &cv);

        float v0 = (a * cv - b * sv) * inv;
        float v1 = (b * cv + a * sv) * inv;
        __nv_bfloat16 h0 = __float2bfloat16(v0);
        __nv_bfloat16 h1 = __float2bfloat16(v1);
        dh[lane]      = h0;
        dh[lane + 32] = h1;
        dl[lane]      = __float2bfloat16(v0 - __bfloat162float(h0));
        dl[lane + 32] = __float2bfloat16(v1 - __bfloat162float(h1));
    } else {
        size_t off = (size_t)t * KV_DIM + 256 + (u - 20) * HDIM;
        const float* src = kv + off;
#pragma unroll
        for (int j = 0; j < 2; j++) {
            float v = src[lane + 32 * j];
            __nv_bfloat16 hh = __float2bfloat16(v);
            kvh[off + lane + 32 * j] = hh;
            kvl[off + lane + 32 * j] = __float2bfloat16(v - __bfloat162float(hh));
        }
    }
}

// ---------------------------------------------------------------------------
// HMMA windowed flash attention, double-buffered K/V. (round-13, passing)
// ---------------------------------------------------------------------------
#define KV_STAGE_BYTES 32768

__global__ __launch_bounds__(128, 2)
void attn_tc(const __nv_bfloat16* __restrict__ qh, const __nv_bfloat16* __restrict__ ql,
             const __nv_bfloat16* __restrict__ kvh, const __nv_bfloat16* __restrict__ kvl,
             __nv_bfloat16* __restrict__ yh, __nv_bfloat16* __restrict__ yl)
{
    __shared__ __align__(16) __nv_bfloat16 sQH[4096], sQL[4096];
    extern __shared__ __align__(16) unsigned char kvsmem[];
    const unsigned kvbase = smem_u32(kvsmem);

    const int mt = blockIdx.x, h = blockIdx.y;
    const int kvhead = h >> 2;
    const int m0 = mt * 64;
    const int tid = threadIdx.x, lane = tid & 31, w = tid >> 5;

    const unsigned uQH = smem_u32(sQH), uQL = smem_u32(sQL);

#pragma unroll
    for (int i = 0; i < 8; i++) {
        int idx = tid + i * 128;
        int buf = idx >> 9, e = idx & 511;
        int r = e >> 3, c = e & 7;
        const __nv_bfloat16* src =
            (buf ? ql : qh) + (size_t)(m0 + r) * C_DIM + h * HDIM + c * 8;
        unsigned dst = (buf ? uQL : uQH) + r * 128 + (((c ^ (r & 7))) << 4);
        cp_async16(dst, src);
    }

    auto fill_kv = [&](int nt, unsigned bufbase) {
        const int n0 = nt * 64;
#pragma unroll
        for (int i = 0; i < 16; i++) {
            int idx = tid + i * 128;
            int tile = idx >> 9;
            int e = idx & 511;
            int r = e >> 3, c = e & 7;
            const __nv_bfloat16* base = (tile & 1) ? kvl : kvh;
            int coloff = (tile < 2) ? (kvhead * HDIM) : (256 + kvhead * HDIM);
            const __nv_bfloat16* src = base + (size_t)(n0 + r) * KV_DIM + coloff + c * 8;
            cp_async16(bufbase + tile * 8192 + r * 128 + (((c ^ (r & 7))) << 4), src);
        }
        asm volatile("cp.async.commit_group;\n" ::: "memory");
    };

    float o[8][4];
    float m_i[2], l_i[2];
#pragma unroll
    for (int nf = 0; nf < 8; nf++)
#pragma unroll
        for (int r = 0; r < 4; r++) o[nf][r] = 0.f;
    m_i[0] = m_i[1] = -1e30f;
    l_i[0] = l_i[1] = 0.f;

    const int arow = lane & 15, aoff = lane >> 4;
    const int brow = (lane & 7) + ((lane >> 4) << 3);
    const int boff = (lane >> 3) & 1;
    const int vrow = (lane & 7) + (((lane >> 3) & 1) << 3);
    const int voff = lane >> 4;

    const int nstart = (mt >= 8) ? (mt - 8) : 0;
    fill_kv(nstart, kvbase);

    for (int nt = nstart; nt <= mt; nt++) {
        const int n0 = nt * 64;
        const int cb = (nt - nstart) & 1;
        const unsigned cur = kvbase + cb * KV_STAGE_BYTES;

        __syncthreads();
        if (nt + 1 <= mt) {
            fill_kv(nt + 1, kvbase + (cb ^ 1) * KV_STAGE_BYTES);
            asm volatile("cp.async.wait_group 1;\n" ::: "memory");
        } else {
            asm volatile("cp.async.wait_group 0;\n" ::: "memory");
        }
        __syncthreads();

        const unsigned uKH = cur, uKL = cur + 8192, uVH = cur + 16384, uVL = cur + 24576;

        float s[8][4];
#pragma unroll
        for (int nf = 0; nf < 8; nf++)
#pragma unroll
            for (int r = 0; r < 4; r++) s[nf][r] = 0.f;

#pragma unroll
        for (int ks = 0; ks < 4; ks++) {
            unsigned ah[4], al[4];
            int ar = 16 * w + arow;
            int ac = ks * 2 + aoff;
            unsigned aaddr = ar * 128 + (((ac ^ (ar & 7))) << 4);
            ldm4(uQH + aaddr, ah[0], ah[1], ah[2], ah[3]);
            ldm4(uQL + aaddr, al[0], al[1], al[2], al[3]);
#pragma unroll
            for (int p = 0; p < 4; p++) {
                unsigned bh[4], bl[4];
                int br = p * 16 + brow;
                int bc = ks * 2 + boff;
                unsigned baddr = br * 128 + (((bc ^ (br & 7))) << 4);
                ldm4(uKH + baddr, bh[0], bh[1], bh[2], bh[3]);
                ldm4(uKL + baddr, bl[0], bl[1], bl[2], bl[3]);
                mma16816(s[2 * p],     ah, bh[0], bh[1]);
                mma16816(s[2 * p],     ah, bl[0], bl[1]);
                mma16816(s[2 * p],     al, bh[0], bh[1]);
                mma16816(s[2 * p + 1], ah, bh[2], bh[3]);
                mma16816(s[2 * p + 1], ah, bl[2], bl[3]);
                mma16816(s[2 * p + 1], al, bh[2], bh[3]);
            }
        }

        const bool needmask = (nt == mt) || (nt == mt - 8);
        const int r0 = m0 + 16 * w + (lane >> 2);
        const int cbase = n0 + 2 * (lane & 3);
#pragma unroll
        for (int nf = 0; nf < 8; nf++)
#pragma unroll
            for (int r = 0; r < 4; r++) {
                float v = s[nf][r] * 0.125f;
                if (needmask) {
                    int qr = r0 + 8 * (r >> 1);
                    int kc = cbase + 8 * nf + (r & 1);
                    if (kc > qr || kc <= qr - WINDOW_SZ) v = -1e30f;
                }
                s[nf][r] = v;
            }

#pragma unroll
        for (int j = 0; j < 2; j++) {
            float tmax = -1e30f;
#pragma unroll
            for (int nf = 0; nf < 8; nf++)
                tmax = fmaxf(tmax, fmaxf(s[nf][2 * j], s[nf][2 * j + 1]));
            tmax = fmaxf(tmax, __shfl_xor_sync(0xffffffffu, tmax, 1));
            tmax = fmaxf(tmax, __shfl_xor_sync(0xffffffffu, tmax, 2));
            float mn = fmaxf(m_i[j], tmax);
            float corr = __expf(m_i[j] - mn);
            m_i[j] = mn;
            float rsum = 0.f;
#pragma unroll
            for (int nf = 0; nf < 8; nf++) {
                float p0 = __expf(s[nf][2 * j] - mn);
                float p1 = __expf(s[nf][2 * j + 1] - mn);
                s[nf][2 * j] = p0;
                s[nf][2 * j + 1] = p1;
                rsum += p0 + p1;
            }
            rsum += __shfl_xor_sync(0xffffffffu, rsum, 1);
            rsum += __shfl_xor_sync(0xffffffffu, rsum, 2);
            l_i[j] = l_i[j] * corr + rsum;
#pragma unroll
            for (int nf = 0; nf < 8; nf++) {
                o[nf][2 * j]     *= corr;
                o[nf][2 * j + 1] *= corr;
            }
        }

#pragma unroll
        for (int kc = 0; kc < 4; kc++) {
            unsigned aph[4], apl[4];
            split2(s[2 * kc][0],     s[2 * kc][1],     aph[0], apl[0]);
            split2(s[2 * kc][2],     s[2 * kc][3],     aph[1], apl[1]);
            split2(s[2 * kc + 1][0], s[2 * kc + 1][1], aph[2], apl[2]);
            split2(s[2 * kc + 1][2], s[2 * kc + 1][3], aph[3], apl[3]);
            int krow = kc * 16 + vrow;
#pragma unroll
            for (int nfb = 0; nfb < 8; nfb += 2) {
                unsigned vh[4], vl[4];
                int chunk = nfb + voff;
                unsigned vaddr = krow * 128 + (((chunk ^ (krow & 7))) << 4);
                ldm4t(uVH + vaddr, vh[0], vh[1], vh[2], vh[3]);
                ldm4t(uVL + vaddr, vl[0], vl[1], vl[2], vl[3]);
                mma16816(o[nfb],     aph, vh[0], vh[1]);
                mma16816(o[nfb],     aph, vl[0], vl[1]);
                mma16816(o[nfb],     apl, vh[0], vh[1]);
                mma16816(o[nfb + 1], aph, vh[2], vh[3]);
                mma16816(o[nfb + 1], aph, vl[2], vl[3]);
                mma16816(o[nfb + 1], apl, vh[2], vh[3]);
            }
        }
    }

    float inv0 = 1.f / l_i[0], inv1 = 1.f / l_i[1];
#pragma unroll
    for (int nf = 0; nf < 8; nf++) {
        int col = h * HDIM + 8 * nf + 2 * (lane & 3);
#pragma unroll
        for (int j = 0; j < 2; j++) {
            int row = m0 + 16 * w + (lane >> 2) + 8 * j;
            float inv = j ? inv1 : inv0;
            float v0 = o[nf][2 * j] * inv, v1 = o[nf][2 * j + 1] * inv;
            unsigned hi, lo;
            split2(v0, v1, hi, lo);
            *reinterpret_cast<unsigned*>(&yh[(size_t)row * C_DIM + col]) = hi;
            *reinterpret_cast<unsigned*>(&yl[(size_t)row * C_DIM + col]) = lo;
        }
    }
}

// ---------------------------------------------------------------------------
extern "C" void kernel_launch(void* const* d_in, const int* in_sizes, int n_in,
                              void* d_out, int out_size)
{
    const float* x     = (const float*)d_in[0];
    const float* Wq    = (const float*)d_in[1];
    const float* Wkv   = (const float*)d_in[2];
    const float* Wproj = (const float*)d_in[3];
    float* out = (float*)d_out;

    float *gq, *gkv;
    cudaGetSymbolAddress((void**)&gq, g_q);
    cudaGetSymbolAddress((void**)&gkv, g_kv);

    __nv_bfloat16 *xh, *xl, *wqkh, *wqkl, *wph, *wpl, *yh, *yl;
    __nv_bfloat16 *qh, *ql, *kvh, *kvl;
    cudaGetSymbolAddress((void**)&xh, g_xh);     cudaGetSymbolAddress((void**)&xl, g_xl);
    cudaGetSymbolAddress((void**)&wqkh, g_wqkh); cudaGetSymbolAddress((void**)&wqkl, g_wqkl);
    cudaGetSymbolAddress((void**)&wph, g_wph);   cudaGetSymbolAddress((void**)&wpl, g_wpl);
    cudaGetSymbolAddress((void**)&yh, g_yh);     cudaGetSymbolAddress((void**)&yl, g_yl);
    cudaGetSymbolAddress((void**)&qh, g_qh);     cudaGetSymbolAddress((void**)&ql, g_ql);
    cudaGetSymbolAddress((void**)&kvh, g_kvh);   cudaGetSymbolAddress((void**)&kvl, g_kvl);

    static bool attr_set = false;
    if (!attr_set) {
        cudaFuncSetAttribute(gemm_tc, cudaFuncAttributeMaxDynamicSharedMemorySize,
                             2 * CHUNK_BYTES);
        cudaFuncSetAttribute(attn_tc, cudaFuncAttributeMaxDynamicSharedMemorySize,
                             2 * KV_STAGE_BYTES);
        attr_set = true;
    }

    const int nx4 = T_SEQ * C_DIM / 4;
    const int nq4 = C_DIM * C_DIM / 4;
    const int nk4 = KV_DIM * C_DIM / 4;
    const int ntot4 = nx4 + 2 * nq4 + nk4;

    // single launch: x, Wq->wqk[0:], Wkv->wqk[1024 rows:], Wproj
    cvt_split4<<<(ntot4 + 255) / 256, 256>>>(
        x, xh, xl, nx4,
        Wq, wqkh, wqkl, nq4,
        Wkv, wqkh + (size_t)C_DIM * C_DIM, wqkl + (size_t)C_DIM * C_DIM, nk4,
        Wproj, wph, wpl, nq4);

    // Fused [Q | KV] = x @ [Wq; Wkv]^T : N = 1536, 192 CTAs
    gemm_tc<<<dim3(1536 / 128, T_SEQ / 128), 256, 2 * CHUNK_BYTES>>>(
        xh, xl, wqkh, wqkl, gq, gkv, C_DIM, C_DIM, KV_DIM);

    // fused norm + rope + split: 8 warps/block, 32 warp-slots per t (24 used)
    norm_rope_split<<<T_SEQ * 32 / 8, 256>>>(gq, gkv, qh, ql, kvh, kvl);

    attn_tc<<<dim3(T_SEQ / 64, HEADS), 128, 2 * KV_STAGE_BYTES>>>(
        qh, ql, kvh, kvl, yh, yl);

    // out = y @ Wproj^T
    gemm_tc<<<dim3(C_DIM / 128, T_SEQ / 128), 256, 2 * CHUNK_BYTES>>>(
        yh, yl, wph, wpl, out, nullptr, 1 << 30, C_DIM, 0);
}